// round 10
// baseline (speedup 1.0000x reference)
#include <cuda_runtime.h>
#include <cuda_bf16.h>
#include <cstdint>

#define N_NODES 100000
#define NFEAT   1433
#define NHID    40
#define NCLASS  7
#define NC_PAD  8
#define E_MAX   3200000
#define SCAN_B  1024
#define SCAN_NBLK ((N_NODES + SCAN_B - 1) / SCAN_B)   // 98

#define M_TILE  128
#define BK      32
#define NCHUNK  ((NFEAT + BK - 1) / BK)   // 45
#define ASTRIDE 40                         // bf16 elems per smem row (32 data + 8 pad), 80B

// ---------------- scratch (device globals; no allocation allowed) -------------
__device__ float g_sup1[N_NODES * NHID];     // x @ W1 (pre-aggregation)
__device__ float g_sup2[N_NODES * NC_PAD];   // h @ W2 (padded to 8)
__device__ int   g_counts[N_NODES];
__device__ int   g_rowptr[N_NODES + 1];
__device__ int   g_pos[N_NODES];
__device__ int   g_blocksum[SCAN_NBLK];
__device__ int   g_blockoff[SCAN_NBLK];
__device__ int2  g_csr_edge[E_MAX];          // (src, weight-bits) grouped by dst

// ---------------- PTX helpers -------------------------------------------------
__device__ __forceinline__ void ldsm4(uint32_t* r, uint32_t addr) {
    asm volatile("ldmatrix.sync.aligned.m8n8.x4.shared.b16 {%0,%1,%2,%3}, [%4];"
        : "=r"(r[0]), "=r"(r[1]), "=r"(r[2]), "=r"(r[3]) : "r"(addr));
}
__device__ __forceinline__ void ldsm2(uint32_t* r, uint32_t addr) {
    asm volatile("ldmatrix.sync.aligned.m8n8.x2.shared.b16 {%0,%1}, [%2];"
        : "=r"(r[0]), "=r"(r[1]) : "r"(addr));
}
__device__ __forceinline__ void mma_bf16(float* d, const uint32_t* a, const uint32_t* b) {
    asm volatile(
        "mma.sync.aligned.m16n8k16.row.col.f32.bf16.bf16.f32 "
        "{%0,%1,%2,%3}, {%4,%5,%6,%7}, {%8,%9}, {%0,%1,%2,%3};"
        : "+f"(d[0]), "+f"(d[1]), "+f"(d[2]), "+f"(d[3])
        : "r"(a[0]), "r"(a[1]), "r"(a[2]), "r"(a[3]), "r"(b[0]), "r"(b[1]));
}

// hi = upper-16-bit truncation of v (exact bf16 bits via shift);
// lo = bf16(v - hi)  -- v-hi computed exactly in fp32; total split err ~2^-16.
__device__ __forceinline__ void split_bf16(float v, uint16_t& hi, uint16_t& lo) {
    uint32_t bits = __float_as_uint(v);
    uint32_t hib  = bits & 0xFFFF0000u;
    hi = (uint16_t)(bits >> 16);
    float rem = v - __uint_as_float(hib);
    __nv_bfloat16 lb = __float2bfloat16(rem);
    lo = *reinterpret_cast<uint16_t*>(&lb);
}

// ---------------- CSR build ---------------------------------------------------
__global__ void clear_counts_kernel() {
    int i = blockIdx.x * blockDim.x + threadIdx.x;
    if (i < N_NODES) g_counts[i] = 0;
}

__global__ void hist_kernel(const int* __restrict__ dst, int E) {
    int e = blockIdx.x * blockDim.x + threadIdx.x;
    if (e < E) atomicAdd(&g_counts[dst[e]], 1);
}

__global__ void __launch_bounds__(SCAN_B) scan_part_kernel() {
    __shared__ int sh[SCAN_B];
    int t = threadIdx.x;
    int i = blockIdx.x * SCAN_B + t;
    int v = (i < N_NODES) ? g_counts[i] : 0;
    sh[t] = v;
    __syncthreads();
    #pragma unroll
    for (int off = 1; off < SCAN_B; off <<= 1) {
        int a = (t >= off) ? sh[t - off] : 0;
        __syncthreads();
        sh[t] += a;
        __syncthreads();
    }
    if (i < N_NODES) g_rowptr[i] = sh[t] - v;
    if (t == SCAN_B - 1) g_blocksum[blockIdx.x] = sh[t];
}

__global__ void scan_top_kernel() {
    __shared__ int sh[128];
    int t = threadIdx.x;
    int v = (t < SCAN_NBLK) ? g_blocksum[t] : 0;
    sh[t] = v;
    __syncthreads();
    #pragma unroll
    for (int off = 1; off < 128; off <<= 1) {
        int a = (t >= off) ? sh[t - off] : 0;
        __syncthreads();
        sh[t] += a;
        __syncthreads();
    }
    if (t < SCAN_NBLK) g_blockoff[t] = sh[t] - v;
}

__global__ void scan_add_kernel(int E) {
    int i = blockIdx.x * blockDim.x + threadIdx.x;
    if (i < N_NODES) {
        int r = g_rowptr[i] + g_blockoff[i >> 10];
        g_rowptr[i] = r;
        g_pos[i] = r;
    }
    if (i == 0) g_rowptr[N_NODES] = E;
}

__global__ void fill_kernel(const int* __restrict__ src, const int* __restrict__ dst,
                            const float* __restrict__ ew, int E) {
    int e = blockIdx.x * blockDim.x + threadIdx.x;
    if (e >= E) return;
    int p = atomicAdd(&g_pos[dst[e]], 1);
    g_csr_edge[p] = make_int2(src[e], __float_as_int(ew[e]));
}

// ---------------- GEMM1 (mma.sync bf16 x3 split): g_sup1 = x @ W1 --------------
// Block 256 thr / 8 warps, tile 128 rows x 40 cols, BK=32.
// Warp w owns rows w*16..w*16+15 (one m16 frag); 5 n8-frags cover N=40.
// Register double-buffer; __launch_bounds__(256,3) forces >=3 CTAs/SM (<=85 regs).
__global__ void __launch_bounds__(256, 3) gemm1_mma_kernel(
    const float* __restrict__ x, const float* __restrict__ W1)
{
    __shared__ __align__(16) __nv_bfloat16 sAhi[M_TILE * ASTRIDE];
    __shared__ __align__(16) __nv_bfloat16 sAlo[M_TILE * ASTRIDE];
    __shared__ __align__(16) __nv_bfloat16 sBhi[NHID * ASTRIDE];
    __shared__ __align__(16) __nv_bfloat16 sBlo[NHID * ASTRIDE];

    const int tid  = threadIdx.x;
    const int wid  = tid >> 5;          // 0..7
    const int lane = tid & 31;
    const int row0 = blockIdx.x * M_TILE;

    float acc[5][4];
    #pragma unroll
    for (int ni = 0; ni < 5; ni++)
        #pragma unroll
        for (int q = 0; q < 4; q++) acc[ni][q] = 0.0f;

    const uint32_t aHiBase = (uint32_t)__cvta_generic_to_shared(sAhi);
    const uint32_t aLoBase = (uint32_t)__cvta_generic_to_shared(sAlo);
    const uint32_t bHiBase = (uint32_t)__cvta_generic_to_shared(sBhi);
    const uint32_t bLoBase = (uint32_t)__cvta_generic_to_shared(sBlo);
    const int g  = lane >> 3;            // 0..3 matrix id (A x4)
    const int rr = lane & 7;
    const uint32_t aOff =
        (uint32_t)(((wid * 16 + (g & 1) * 8 + rr) * ASTRIDE + (g >> 1) * 8) * 2);
    uint32_t bOff[5];
    #pragma unroll
    for (int ni = 0; ni < 5; ni++)
        bOff[ni] = (uint32_t)(((ni * 8 + rr) * ASTRIDE + ((lane >> 3) & 1) * 8) * 2);

    // A fill mapping: lane = k, rows wid + it*8 (coalesced: 1 line per warp-LDG)
    // B fill mapping: idx = tid + it*256 -> k = idx/40, n = idx%40
    float pa[16];
    float pb[5];

    // ---- prefetch chunk 0 ----
    {
        const int gk = lane;   // k0 = 0
        #pragma unroll
        for (int it = 0; it < 16; it++) {
            int gr = row0 + wid + it * 8;
            pa[it] = (gr < N_NODES) ? __ldg(x + (size_t)gr * NFEAT + gk) : 0.0f;
        }
        #pragma unroll
        for (int it = 0; it < 5; it++) {
            int idx = tid + it * 256;
            int k2 = idx / NHID, nn = idx - k2 * NHID;
            pb[it] = __ldg(W1 + (size_t)k2 * NHID + nn);
        }
    }

    for (int c = 0; c < NCHUNK; c++) {
        // ---- store prefetched regs to smem (bf16 hi/lo via bit-split) ----
        #pragma unroll
        for (int it = 0; it < 16; it++) {
            int r = wid + it * 8;
            uint16_t hi, lo;
            split_bf16(pa[it], hi, lo);
            *reinterpret_cast<uint16_t*>(&sAhi[r * ASTRIDE + lane]) = hi;
            *reinterpret_cast<uint16_t*>(&sAlo[r * ASTRIDE + lane]) = lo;
        }
        #pragma unroll
        for (int it = 0; it < 5; it++) {
            int idx = tid + it * 256;
            int k2 = idx / NHID, nn = idx - k2 * NHID;
            uint16_t hi, lo;
            split_bf16(pb[it], hi, lo);
            *reinterpret_cast<uint16_t*>(&sBhi[nn * ASTRIDE + k2]) = hi;
            *reinterpret_cast<uint16_t*>(&sBlo[nn * ASTRIDE + k2]) = lo;
        }
        __syncthreads();

        // ---- issue next chunk's global loads (overlap with MMAs below) ----
        if (c + 1 < NCHUNK) {
            const int k0n = (c + 1) * BK;
            const int gk = k0n + lane;
            const bool kok = (gk < NFEAT);
            #pragma unroll
            for (int it = 0; it < 16; it++) {
                int gr = row0 + wid + it * 8;
                pa[it] = (kok && gr < N_NODES) ? __ldg(x + (size_t)gr * NFEAT + gk) : 0.0f;
            }
            #pragma unroll
            for (int it = 0; it < 5; it++) {
                int idx = tid + it * 256;
                int k2 = idx / NHID, nn = idx - k2 * NHID;
                int gk2 = k0n + k2;
                pb[it] = (gk2 < NFEAT) ? __ldg(W1 + (size_t)gk2 * NHID + nn) : 0.0f;
            }
        }

        // ---- MMAs for current chunk ----
        #pragma unroll
        for (int ks = 0; ks < 2; ks++) {
            const uint32_t kb = (uint32_t)(ks * 16 * 2);  // 16 bf16 = 32B
            uint32_t ahi[4], alo[4], bhi[5][2], blo[5][2];
            ldsm4(ahi, aHiBase + aOff + kb);
            ldsm4(alo, aLoBase + aOff + kb);
            #pragma unroll
            for (int ni = 0; ni < 5; ni++) {
                ldsm2(bhi[ni], bHiBase + bOff[ni] + kb);
                ldsm2(blo[ni], bLoBase + bOff[ni] + kb);
            }
            #pragma unroll
            for (int ni = 0; ni < 5; ni++) {
                mma_bf16(acc[ni], ahi, bhi[ni]);
                mma_bf16(acc[ni], ahi, blo[ni]);
                mma_bf16(acc[ni], alo, bhi[ni]);
            }
        }
        __syncthreads();
    }

    // ---- writeout: warp w rows w*16 + lane/4 (+8), cols ni*8 + (lane%4)*2 ----
    const int rbase = row0 + wid * 16 + (lane >> 2);
    const int cbase = (lane & 3) * 2;
    #pragma unroll
    for (int ni = 0; ni < 5; ni++) {
        int col = ni * 8 + cbase;
        if (rbase < N_NODES) {
            float2 v = make_float2(acc[ni][0], acc[ni][1]);
            *(float2*)(g_sup1 + (size_t)rbase * NHID + col) = v;
        }
        if (rbase + 8 < N_NODES) {
            float2 v = make_float2(acc[ni][2], acc[ni][3]);
            *(float2*)(g_sup1 + (size_t)(rbase + 8) * NHID + col) = v;
        }
    }
}

// ------- agg1 + bias/relu/dropout + GEMM2 fused (warp per node) ---------------
__global__ void __launch_bounds__(256) agg1_gemm2_kernel(
    const float* __restrict__ b1, const float* __restrict__ mask,
    const float* __restrict__ W2)
{
    __shared__ float w2s[NHID * NCLASS];   // 280, row-major [k][c]
    for (int i = threadIdx.x; i < NHID * NCLASS; i += 256) w2s[i] = W2[i];
    __syncthreads();

    int n = (blockIdx.x * blockDim.x + threadIdx.x) >> 5;
    int lane = threadIdx.x & 31;
    if (n >= N_NODES) return;
    int beg = g_rowptr[n], end = g_rowptr[n + 1];

    float acc0 = 0.0f, acc1 = 0.0f;
    #pragma unroll 1
    for (int e0 = beg; e0 < end; e0 += 4) {
        int2 ed[4];
        #pragma unroll
        for (int j = 0; j < 4; j++) {
            int idx = e0 + j;
            ed[j] = (idx < end) ? __ldg(&g_csr_edge[idx]) : make_int2(0, 0);
        }
        #pragma unroll
        for (int j = 0; j < 4; j++) {
            float w = __int_as_float(ed[j].y);
            const float* row = g_sup1 + (size_t)ed[j].x * NHID;
            acc0 = fmaf(w, __ldg(row + lane), acc0);
            if (lane < 8) acc1 = fmaf(w, __ldg(row + 32 + lane), acc1);
        }
    }
    float h0, h1v = 0.0f;
    {
        float v = fmaxf(acc0 + __ldg(b1 + lane), 0.0f);
        float m = __ldg(mask + (size_t)n * NHID + lane);
        h0 = (m > 0.5f) ? v * 2.0f : 0.0f;
    }
    if (lane < 8) {
        int cidx = 32 + lane;
        float v = fmaxf(acc1 + __ldg(b1 + cidx), 0.0f);
        float m = __ldg(mask + (size_t)n * NHID + cidx);
        h1v = (m > 0.5f) ? v * 2.0f : 0.0f;
    }
    #pragma unroll
    for (int c = 0; c < NCLASS; c++) {
        float p = h0 * w2s[lane * NCLASS + c];
        if (lane < 8) p += h1v * w2s[(32 + lane) * NCLASS + c];
        p += __shfl_xor_sync(0xFFFFFFFFu, p, 16);
        p += __shfl_xor_sync(0xFFFFFFFFu, p, 8);
        p += __shfl_xor_sync(0xFFFFFFFFu, p, 4);
        p += __shfl_xor_sync(0xFFFFFFFFu, p, 2);
        p += __shfl_xor_sync(0xFFFFFFFFu, p, 1);
        if (lane == 0) g_sup2[(size_t)n * NC_PAD + c] = p;
    }
    if (lane == 0) g_sup2[(size_t)n * NC_PAD + NCLASS] = 0.0f;  // pad
}

// ------- agg2 (warp/node, 4 edges x 8 feats) fused with bias + log_softmax ----
__global__ void __launch_bounds__(256) agg2_lsm_kernel(
    const float* __restrict__ b2, float* __restrict__ out)
{
    int n = (blockIdx.x * blockDim.x + threadIdx.x) >> 5;
    int lane = threadIdx.x & 31;
    if (n >= N_NODES) return;
    int beg = g_rowptr[n], end = g_rowptr[n + 1];
    int j = lane >> 3;      // edge sub-slot 0..3
    int f = lane & 7;       // feature 0..7 (7 = pad)

    float acc = 0.0f;
    #pragma unroll 1
    for (int e0 = beg; e0 < end; e0 += 4) {
        int idx = e0 + j;
        int2 ed = (idx < end) ? __ldg(&g_csr_edge[idx]) : make_int2(0, 0);
        float w = __int_as_float(ed.y);
        acc = fmaf(w, __ldg(g_sup2 + (size_t)ed.x * NC_PAD + f), acc);
    }
    acc += __shfl_xor_sync(0xFFFFFFFFu, acc, 8);
    acc += __shfl_xor_sync(0xFFFFFFFFu, acc, 16);

    float z = acc + __ldg(b2 + ((f < NCLASS) ? f : 0));
    float m = (f < NCLASS) ? z : -1e30f;
    m = fmaxf(m, __shfl_xor_sync(0xFFFFFFFFu, m, 1));
    m = fmaxf(m, __shfl_xor_sync(0xFFFFFFFFu, m, 2));
    m = fmaxf(m, __shfl_xor_sync(0xFFFFFFFFu, m, 4));
    float ex = (f < NCLASS) ? __expf(z - m) : 0.0f;
    float s = ex;
    s += __shfl_xor_sync(0xFFFFFFFFu, s, 1);
    s += __shfl_xor_sync(0xFFFFFFFFu, s, 2);
    s += __shfl_xor_sync(0xFFFFFFFFu, s, 4);
    float lse = m + __logf(s);
    if (f < NCLASS && j == 0)
        out[(size_t)n * NCLASS + f] = z - lse;
}

// ---------------- launch -----------------------------------------------------
extern "C" void kernel_launch(void* const* d_in, const int* in_sizes, int n_in,
                              void* d_out, int out_size)
{
    const float* x    = (const float*)d_in[0];
    const int*   src  = (const int*)  d_in[1];
    const int*   dst  = (const int*)  d_in[2];
    const float* ew   = (const float*)d_in[3];
    const float* W1   = (const float*)d_in[4];
    const float* b1   = (const float*)d_in[5];
    const float* W2   = (const float*)d_in[6];
    const float* b2   = (const float*)d_in[7];
    const float* mask = (const float*)d_in[8];
    float* out = (float*)d_out;

    const int E = in_sizes[1];
    const int NBLK_M = (N_NODES + M_TILE - 1) / M_TILE;   // 782

    // gemm1 stays at launch index 3 (captured by ncu -s/-c).             idx
    clear_counts_kernel<<<(N_NODES + 255) / 256, 256>>>();              //  0
    hist_kernel<<<(E + 255) / 256, 256>>>(dst, E);                      //  1
    scan_part_kernel<<<SCAN_NBLK, SCAN_B>>>();                          //  2
    gemm1_mma_kernel<<<NBLK_M, 256>>>(x, W1);                           //  3  <- profiled
    scan_top_kernel<<<1, 128>>>();                                      //  4
    scan_add_kernel<<<(N_NODES + 255) / 256, 256>>>(E);                 //  5
    fill_kernel<<<(E + 255) / 256, 256>>>(src, dst, ew, E);             //  6
    agg1_gemm2_kernel<<<(N_NODES * 32 + 255) / 256, 256>>>(b1, mask, W2); // 7
    agg2_lsm_kernel<<<(N_NODES * 32 + 255) / 256, 256>>>(b2, out);      //  8
}

// round 11
// speedup vs baseline: 1.0806x; 1.0806x over previous
#include <cuda_runtime.h>
#include <cuda_bf16.h>
#include <cstdint>

#define N_NODES 100000
#define NFEAT   1433
#define NHID    40
#define NCLASS  7
#define NC_PAD  8
#define E_MAX   3200000
#define SCAN_B  1024
#define SCAN_NBLK ((N_NODES + SCAN_B - 1) / SCAN_B)   // 98

#define M_TILE  128
#define BK      32
#define NCHUNK  ((NFEAT + BK - 1) / BK)   // 45
#define ASTRIDE 40                         // bf16 elems per smem row (32 data + 8 pad), 80B

// ---------------- scratch (device globals; no allocation allowed) -------------
__device__ float g_sup1[N_NODES * NHID];     // x @ W1 (pre-aggregation)
__device__ float g_sup2[N_NODES * NC_PAD];   // h @ W2 (padded to 8)
__device__ int   g_counts[N_NODES];
__device__ int   g_rowptr[N_NODES + 1];
__device__ int   g_pos[N_NODES];
__device__ int   g_blocksum[SCAN_NBLK];
__device__ int   g_blockoff[SCAN_NBLK];
__device__ int2  g_csr_edge[E_MAX];          // (src, weight-bits) grouped by dst

// ---------------- PTX helpers -------------------------------------------------
__device__ __forceinline__ void ldsm4(uint32_t* r, uint32_t addr) {
    asm volatile("ldmatrix.sync.aligned.m8n8.x4.shared.b16 {%0,%1,%2,%3}, [%4];"
        : "=r"(r[0]), "=r"(r[1]), "=r"(r[2]), "=r"(r[3]) : "r"(addr));
}
__device__ __forceinline__ void ldsm2(uint32_t* r, uint32_t addr) {
    asm volatile("ldmatrix.sync.aligned.m8n8.x2.shared.b16 {%0,%1}, [%2];"
        : "=r"(r[0]), "=r"(r[1]) : "r"(addr));
}
__device__ __forceinline__ void mma_bf16(float* d, const uint32_t* a, const uint32_t* b) {
    asm volatile(
        "mma.sync.aligned.m16n8k16.row.col.f32.bf16.bf16.f32 "
        "{%0,%1,%2,%3}, {%4,%5,%6,%7}, {%8,%9}, {%0,%1,%2,%3};"
        : "+f"(d[0]), "+f"(d[1]), "+f"(d[2]), "+f"(d[3])
        : "r"(a[0]), "r"(a[1]), "r"(a[2]), "r"(a[3]), "r"(b[0]), "r"(b[1]));
}

// hi = upper-16-bit truncation (exact bf16 bits); lo = bf16(v - hi).
__device__ __forceinline__ void split_bf16(float v, uint16_t& hi, uint16_t& lo) {
    uint32_t bits = __float_as_uint(v);
    uint32_t hib  = bits & 0xFFFF0000u;
    hi = (uint16_t)(bits >> 16);
    float rem = v - __uint_as_float(hib);
    __nv_bfloat16 lb = __float2bfloat16(rem);
    lo = *reinterpret_cast<uint16_t*>(&lb);
}

// ---------------- CSR build ---------------------------------------------------
__global__ void clear_counts_kernel() {
    int i = blockIdx.x * blockDim.x + threadIdx.x;
    if (i < N_NODES) g_counts[i] = 0;
}

__global__ void hist_kernel(const int* __restrict__ dst, int E) {
    int e = blockIdx.x * blockDim.x + threadIdx.x;
    if (e < E) atomicAdd(&g_counts[dst[e]], 1);
}

__global__ void __launch_bounds__(SCAN_B) scan_part_kernel() {
    __shared__ int sh[SCAN_B];
    int t = threadIdx.x;
    int i = blockIdx.x * SCAN_B + t;
    int v = (i < N_NODES) ? g_counts[i] : 0;
    sh[t] = v;
    __syncthreads();
    #pragma unroll
    for (int off = 1; off < SCAN_B; off <<= 1) {
        int a = (t >= off) ? sh[t - off] : 0;
        __syncthreads();
        sh[t] += a;
        __syncthreads();
    }
    if (i < N_NODES) g_rowptr[i] = sh[t] - v;
    if (t == SCAN_B - 1) g_blocksum[blockIdx.x] = sh[t];
}

__global__ void scan_top_kernel() {
    __shared__ int sh[128];
    int t = threadIdx.x;
    int v = (t < SCAN_NBLK) ? g_blocksum[t] : 0;
    sh[t] = v;
    __syncthreads();
    #pragma unroll
    for (int off = 1; off < 128; off <<= 1) {
        int a = (t >= off) ? sh[t - off] : 0;
        __syncthreads();
        sh[t] += a;
        __syncthreads();
    }
    if (t < SCAN_NBLK) g_blockoff[t] = sh[t] - v;
}

__global__ void scan_add_kernel(int E) {
    int i = blockIdx.x * blockDim.x + threadIdx.x;
    if (i < N_NODES) {
        int r = g_rowptr[i] + g_blockoff[i >> 10];
        g_rowptr[i] = r;
        g_pos[i] = r;
    }
    if (i == 0) g_rowptr[N_NODES] = E;
}

__global__ void fill_kernel(const int* __restrict__ src, const int* __restrict__ dst,
                            const float* __restrict__ ew, int E) {
    int e = blockIdx.x * blockDim.x + threadIdx.x;
    if (e >= E) return;
    int p = atomicAdd(&g_pos[dst[e]], 1);
    g_csr_edge[p] = make_int2(src[e], __float_as_int(ew[e]));
}

// ---------------- GEMM1 (mma.sync bf16 x3 split): g_sup1 = x @ W1 --------------
// Block 256 thr / 8 warps, tile 128 rows x 40 cols, BK=32.
// Smem DOUBLE-buffered, one __syncthreads per chunk:
//   LDG(c+1) -> MMA(c, buf) -> STS(c+1, other buf) -> sync.
__global__ void __launch_bounds__(256) gemm1_mma_kernel(
    const float* __restrict__ x, const float* __restrict__ W1)
{
    __shared__ __align__(16) uint16_t sAhi[2][M_TILE * ASTRIDE];
    __shared__ __align__(16) uint16_t sAlo[2][M_TILE * ASTRIDE];
    __shared__ __align__(16) uint16_t sBhi[2][NHID * ASTRIDE];
    __shared__ __align__(16) uint16_t sBlo[2][NHID * ASTRIDE];

    const int tid  = threadIdx.x;
    const int wid  = tid >> 5;          // 0..7
    const int lane = tid & 31;
    const int row0 = blockIdx.x * M_TILE;

    float acc[5][4];
    #pragma unroll
    for (int ni = 0; ni < 5; ni++)
        #pragma unroll
        for (int q = 0; q < 4; q++) acc[ni][q] = 0.0f;

    const int g  = lane >> 3;            // 0..3 matrix id
    const int rr = lane & 7;
    // A x4 frag: rows wid*16 + (g&1)*8 + rr, col-half (g>>1)*8
    const uint32_t aOff =
        (uint32_t)(((wid * 16 + (g & 1) * 8 + rr) * ASTRIDE + (g >> 1) * 8) * 2);
    // B x4 frag pair (ni, ni+1): matrix g -> n-frag ni+(g>>1), col-half (g&1)*8
    // bOff4[p] for p=0 (ni=0,1) and p=1 (ni=2,3); bOff2 for ni=4
    uint32_t bOff4[2];
    #pragma unroll
    for (int p = 0; p < 2; p++)
        bOff4[p] = (uint32_t)((((p * 2 + (g >> 1)) * 8 + rr) * ASTRIDE + (g & 1) * 8) * 2);
    const uint32_t bOff2 =
        (uint32_t)(((4 * 8 + rr) * ASTRIDE + ((lane >> 3) & 1) * 8) * 2);

    float pa[16];
    float pb[5];

    // ---- prefetch chunk 0 (A: lane=k, rows wid+it*8 coalesced; B: idx=tid+it*256)
    {
        const int gk = lane;
        #pragma unroll
        for (int it = 0; it < 16; it++) {
            int gr = row0 + wid + it * 8;
            pa[it] = (gr < N_NODES) ? __ldg(x + (size_t)gr * NFEAT + gk) : 0.0f;
        }
        #pragma unroll
        for (int it = 0; it < 5; it++) {
            int idx = tid + it * 256;
            int k2 = idx / NHID, nn = idx - k2 * NHID;
            pb[it] = __ldg(W1 + (size_t)k2 * NHID + nn);
        }
    }
    // ---- store chunk 0 into buffer 0 ----
    #pragma unroll
    for (int it = 0; it < 16; it++) {
        int r = wid + it * 8;
        uint16_t hi, lo;
        split_bf16(pa[it], hi, lo);
        sAhi[0][r * ASTRIDE + lane] = hi;
        sAlo[0][r * ASTRIDE + lane] = lo;
    }
    #pragma unroll
    for (int it = 0; it < 5; it++) {
        int idx = tid + it * 256;
        int k2 = idx / NHID, nn = idx - k2 * NHID;
        uint16_t hi, lo;
        split_bf16(pb[it], hi, lo);
        sBhi[0][nn * ASTRIDE + k2] = hi;
        sBlo[0][nn * ASTRIDE + k2] = lo;
    }
    __syncthreads();

    for (int c = 0; c < NCHUNK; c++) {
        const int cur = c & 1;
        const bool more = (c + 1 < NCHUNK);

        // ---- LDG chunk c+1 (latency covered by MMAs below) ----
        if (more) {
            const int k0n = (c + 1) * BK;
            const int gk = k0n + lane;
            const bool kok = (gk < NFEAT);
            #pragma unroll
            for (int it = 0; it < 16; it++) {
                int gr = row0 + wid + it * 8;
                pa[it] = (kok && gr < N_NODES) ? __ldg(x + (size_t)gr * NFEAT + gk) : 0.0f;
            }
            #pragma unroll
            for (int it = 0; it < 5; it++) {
                int idx = tid + it * 256;
                int k2 = idx / NHID, nn = idx - k2 * NHID;
                int gk2 = k0n + k2;
                pb[it] = (gk2 < NFEAT) ? __ldg(W1 + (size_t)gk2 * NHID + nn) : 0.0f;
            }
        }

        // ---- MMAs for chunk c from buf[cur] ----
        const uint32_t aHiB = (uint32_t)__cvta_generic_to_shared(sAhi[cur]);
        const uint32_t aLoB = (uint32_t)__cvta_generic_to_shared(sAlo[cur]);
        const uint32_t bHiB = (uint32_t)__cvta_generic_to_shared(sBhi[cur]);
        const uint32_t bLoB = (uint32_t)__cvta_generic_to_shared(sBlo[cur]);
        #pragma unroll
        for (int ks = 0; ks < 2; ks++) {
            const uint32_t kb = (uint32_t)(ks * 16 * 2);  // 16 bf16 = 32B
            uint32_t ahi[4], alo[4], bhi[6], blo[6];      // bhi[2i..2i+1] = frag ni=i
            ldsm4(ahi, aHiB + aOff + kb);
            ldsm4(alo, aLoB + aOff + kb);
            ldsm4(bhi + 0, bHiB + bOff4[0] + kb);   // ni 0,1
            ldsm4(bhi + 4 - 4 + 4, bHiB + bOff4[1] + kb); // ni 2,3 -> bhi[4],bhi[5]... need 8 slots
            // (see expanded arrays below)
            (void)bhi; (void)blo;
            // -- replaced by explicit code below --
            uint32_t bh[10], bl[10];
            ldsm4(bh + 0, bHiB + bOff4[0] + kb);    // frags ni=0 (bh0,bh1), ni=1 (bh2,bh3)
            ldsm4(bh + 4, bHiB + bOff4[1] + kb);    // frags ni=2,3
            ldsm2(bh + 8, bHiB + bOff2 + kb);       // frag  ni=4
            ldsm4(bl + 0, bLoB + bOff4[0] + kb);
            ldsm4(bl + 4, bLoB + bOff4[1] + kb);
            ldsm2(bl + 8, bLoB + bOff2 + kb);
            #pragma unroll
            for (int ni = 0; ni < 5; ni++) {
                mma_bf16(acc[ni], ahi, bh + ni * 2);
                mma_bf16(acc[ni], ahi, bl + ni * 2);
                mma_bf16(acc[ni], alo, bh + ni * 2);
            }
        }

        // ---- STS chunk c+1 into buf[cur^1] (safe: MMA(c-1) on that buf done
        //      before previous iteration's sync) ----
        if (more) {
            const int nxt = cur ^ 1;
            #pragma unroll
            for (int it = 0; it < 16; it++) {
                int r = wid + it * 8;
                uint16_t hi, lo;
                split_bf16(pa[it], hi, lo);
                sAhi[nxt][r * ASTRIDE + lane] = hi;
                sAlo[nxt][r * ASTRIDE + lane] = lo;
            }
            #pragma unroll
            for (int it = 0; it < 5; it++) {
                int idx = tid + it * 256;
                int k2 = idx / NHID, nn = idx - k2 * NHID;
                uint16_t hi, lo;
                split_bf16(pb[it], hi, lo);
                sBhi[nxt][nn * ASTRIDE + k2] = hi;
                sBlo[nxt][nn * ASTRIDE + k2] = lo;
            }
        }
        __syncthreads();
    }

    // ---- writeout: warp w rows w*16 + lane/4 (+8), cols ni*8 + (lane%4)*2 ----
    const int rbase = row0 + wid * 16 + (lane >> 2);
    const int cbase = (lane & 3) * 2;
    #pragma unroll
    for (int ni = 0; ni < 5; ni++) {
        int col = ni * 8 + cbase;
        if (rbase < N_NODES) {
            float2 v = make_float2(acc[ni][0], acc[ni][1]);
            *(float2*)(g_sup1 + (size_t)rbase * NHID + col) = v;
        }
        if (rbase + 8 < N_NODES) {
            float2 v = make_float2(acc[ni][2], acc[ni][3]);
            *(float2*)(g_sup1 + (size_t)(rbase + 8) * NHID + col) = v;
        }
    }
}

// ------- agg1 + bias/relu/dropout + GEMM2 fused (warp per node) ---------------
__global__ void __launch_bounds__(256) agg1_gemm2_kernel(
    const float* __restrict__ b1, const float* __restrict__ mask,
    const float* __restrict__ W2)
{
    __shared__ float w2s[NHID * NCLASS];   // 280, row-major [k][c]
    for (int i = threadIdx.x; i < NHID * NCLASS; i += 256) w2s[i] = W2[i];
    __syncthreads();

    int n = (blockIdx.x * blockDim.x + threadIdx.x) >> 5;
    int lane = threadIdx.x & 31;
    if (n >= N_NODES) return;
    int beg = g_rowptr[n], end = g_rowptr[n + 1];

    float acc0 = 0.0f, acc1 = 0.0f;
    #pragma unroll 1
    for (int e0 = beg; e0 < end; e0 += 4) {
        int2 ed[4];
        #pragma unroll
        for (int j = 0; j < 4; j++) {
            int idx = e0 + j;
            ed[j] = (idx < end) ? __ldg(&g_csr_edge[idx]) : make_int2(0, 0);
        }
        #pragma unroll
        for (int j = 0; j < 4; j++) {
            float w = __int_as_float(ed[j].y);
            const float* row = g_sup1 + (size_t)ed[j].x * NHID;
            acc0 = fmaf(w, __ldg(row + lane), acc0);
            if (lane < 8) acc1 = fmaf(w, __ldg(row + 32 + lane), acc1);
        }
    }
    float h0, h1v = 0.0f;
    {
        float v = fmaxf(acc0 + __ldg(b1 + lane), 0.0f);
        float m = __ldg(mask + (size_t)n * NHID + lane);
        h0 = (m > 0.5f) ? v * 2.0f : 0.0f;
    }
    if (lane < 8) {
        int cidx = 32 + lane;
        float v = fmaxf(acc1 + __ldg(b1 + cidx), 0.0f);
        float m = __ldg(mask + (size_t)n * NHID + cidx);
        h1v = (m > 0.5f) ? v * 2.0f : 0.0f;
    }
    #pragma unroll
    for (int c = 0; c < NCLASS; c++) {
        float p = h0 * w2s[lane * NCLASS + c];
        if (lane < 8) p += h1v * w2s[(32 + lane) * NCLASS + c];
        p += __shfl_xor_sync(0xFFFFFFFFu, p, 16);
        p += __shfl_xor_sync(0xFFFFFFFFu, p, 8);
        p += __shfl_xor_sync(0xFFFFFFFFu, p, 4);
        p += __shfl_xor_sync(0xFFFFFFFFu, p, 2);
        p += __shfl_xor_sync(0xFFFFFFFFu, p, 1);
        if (lane == 0) g_sup2[(size_t)n * NC_PAD + c] = p;
    }
    if (lane == 0) g_sup2[(size_t)n * NC_PAD + NCLASS] = 0.0f;  // pad
}

// ------- agg2 (warp/node, 4 edges x 8 feats) fused with bias + log_softmax ----
__global__ void __launch_bounds__(256) agg2_lsm_kernel(
    const float* __restrict__ b2, float* __restrict__ out)
{
    int n = (blockIdx.x * blockDim.x + threadIdx.x) >> 5;
    int lane = threadIdx.x & 31;
    if (n >= N_NODES) return;
    int beg = g_rowptr[n], end = g_rowptr[n + 1];
    int j = lane >> 3;      // edge sub-slot 0..3
    int f = lane & 7;       // feature 0..7 (7 = pad)

    float acc = 0.0f;
    #pragma unroll 1
    for (int e0 = beg; e0 < end; e0 += 4) {
        int idx = e0 + j;
        int2 ed = (idx < end) ? __ldg(&g_csr_edge[idx]) : make_int2(0, 0);
        float w = __int_as_float(ed.y);
        acc = fmaf(w, __ldg(g_sup2 + (size_t)ed.x * NC_PAD + f), acc);
    }
    acc += __shfl_xor_sync(0xFFFFFFFFu, acc, 8);
    acc += __shfl_xor_sync(0xFFFFFFFFu, acc, 16);

    float z = acc + __ldg(b2 + ((f < NCLASS) ? f : 0));
    float m = (f < NCLASS) ? z : -1e30f;
    m = fmaxf(m, __shfl_xor_sync(0xFFFFFFFFu, m, 1));
    m = fmaxf(m, __shfl_xor_sync(0xFFFFFFFFu, m, 2));
    m = fmaxf(m, __shfl_xor_sync(0xFFFFFFFFu, m, 4));
    float ex = (f < NCLASS) ? __expf(z - m) : 0.0f;
    float s = ex;
    s += __shfl_xor_sync(0xFFFFFFFFu, s, 1);
    s += __shfl_xor_sync(0xFFFFFFFFu, s, 2);
    s += __shfl_xor_sync(0xFFFFFFFFu, s, 4);
    float lse = m + __logf(s);
    if (f < NCLASS && j == 0)
        out[(size_t)n * NCLASS + f] = z - lse;
}

// ---------------- launch -----------------------------------------------------
extern "C" void kernel_launch(void* const* d_in, const int* in_sizes, int n_in,
                              void* d_out, int out_size)
{
    const float* x    = (const float*)d_in[0];
    const int*   src  = (const int*)  d_in[1];
    const int*   dst  = (const int*)  d_in[2];
    const float* ew   = (const float*)d_in[3];
    const float* W1   = (const float*)d_in[4];
    const float* b1   = (const float*)d_in[5];
    const float* W2   = (const float*)d_in[6];
    const float* b2   = (const float*)d_in[7];
    const float* mask = (const float*)d_in[8];
    float* out = (float*)d_out;

    const int E = in_sizes[1];
    const int NBLK_M = (N_NODES + M_TILE - 1) / M_TILE;   // 782

    // gemm1 stays at launch index 3 (captured by ncu -s/-c).             idx
    clear_counts_kernel<<<(N_NODES + 255) / 256, 256>>>();              //  0
    hist_kernel<<<(E + 255) / 256, 256>>>(dst, E);                      //  1
    scan_part_kernel<<<SCAN_NBLK, SCAN_B>>>();                          //  2
    gemm1_mma_kernel<<<NBLK_M, 256>>>(x, W1);                           //  3  <- profiled
    scan_top_kernel<<<1, 128>>>();                                      //  4
    scan_add_kernel<<<(N_NODES + 255) / 256, 256>>>(E);                 //  5
    fill_kernel<<<(E + 255) / 256, 256>>>(src, dst, ew, E);             //  6
    agg1_gemm2_kernel<<<(N_NODES * 32 + 255) / 256, 256>>>(b1, mask, W2); // 7
    agg2_lsm_kernel<<<(N_NODES * 32 + 255) / 256, 256>>>(b2, out);      //  8
}

// round 12
// speedup vs baseline: 1.1570x; 1.0707x over previous
#include <cuda_runtime.h>
#include <cuda_bf16.h>
#include <cstdint>

#define N_NODES 100000
#define NFEAT   1433
#define NHID    40
#define NCLASS  7
#define NC_PAD  8
#define E_MAX   3200000
#define SCAN_B  1024
#define SCAN_NBLK ((N_NODES + SCAN_B - 1) / SCAN_B)   // 98

#define M_TILE  128
#define BK      32
#define NCHUNK  ((NFEAT + BK - 1) / BK)   // 45
#define ASTRIDE 40                         // A smem: bf16 elems per row (80B, 16B-mult)
#define W1_TOT  (NFEAT * NHID)             // 57320

// ---------------- scratch (device globals; no allocation allowed) -------------
__device__ float g_sup1[N_NODES * NHID];     // x @ W1 (pre-aggregation)
__device__ float g_sup2[N_NODES * NC_PAD];   // h @ W2 (padded to 8)
__device__ int   g_counts[N_NODES];
__device__ int   g_rowptr[N_NODES + 1];
__device__ int   g_pos[N_NODES];
__device__ int   g_blocksum[SCAN_NBLK];
__device__ int   g_blockoff[SCAN_NBLK];
__device__ int2  g_csr_edge[E_MAX];          // (src, weight-bits) grouped by dst

// ---------------- PTX helpers -------------------------------------------------
__device__ __forceinline__ void ldsm4(uint32_t* r, uint32_t addr) {
    asm volatile("ldmatrix.sync.aligned.m8n8.x4.shared.b16 {%0,%1,%2,%3}, [%4];"
        : "=r"(r[0]), "=r"(r[1]), "=r"(r[2]), "=r"(r[3]) : "r"(addr));
}
__device__ __forceinline__ void ldsm4t(uint32_t* r, uint32_t addr) {
    asm volatile("ldmatrix.sync.aligned.m8n8.x4.trans.shared.b16 {%0,%1,%2,%3}, [%4];"
        : "=r"(r[0]), "=r"(r[1]), "=r"(r[2]), "=r"(r[3]) : "r"(addr));
}
__device__ __forceinline__ void ldsm2t(uint32_t* r, uint32_t addr) {
    asm volatile("ldmatrix.sync.aligned.m8n8.x2.trans.shared.b16 {%0,%1}, [%2];"
        : "=r"(r[0]), "=r"(r[1]) : "r"(addr));
}
__device__ __forceinline__ void mma_bf16(float* d, const uint32_t* a, const uint32_t* b) {
    asm volatile(
        "mma.sync.aligned.m16n8k16.row.col.f32.bf16.bf16.f32 "
        "{%0,%1,%2,%3}, {%4,%5,%6,%7}, {%8,%9}, {%0,%1,%2,%3};"
        : "+f"(d[0]), "+f"(d[1]), "+f"(d[2]), "+f"(d[3])
        : "r"(a[0]), "r"(a[1]), "r"(a[2]), "r"(a[3]), "r"(b[0]), "r"(b[1]));
}

// hi = upper-16-bit truncation (exact bf16 bits); lo = bf16(v - hi).
__device__ __forceinline__ void split_bf16(float v, uint16_t& hi, uint16_t& lo) {
    uint32_t bits = __float_as_uint(v);
    uint32_t hib  = bits & 0xFFFF0000u;
    hi = (uint16_t)(bits >> 16);
    float rem = v - __uint_as_float(hib);
    __nv_bfloat16 lb = __float2bfloat16(rem);
    lo = *reinterpret_cast<uint16_t*>(&lb);
}

// ---------------- CSR build ---------------------------------------------------
__global__ void clear_counts_kernel() {
    int i = blockIdx.x * blockDim.x + threadIdx.x;
    if (i < N_NODES) g_counts[i] = 0;
}

__global__ void hist_kernel(const int* __restrict__ dst, int E) {
    int e = blockIdx.x * blockDim.x + threadIdx.x;
    if (e < E) atomicAdd(&g_counts[dst[e]], 1);
}

__global__ void __launch_bounds__(SCAN_B) scan_part_kernel() {
    __shared__ int sh[SCAN_B];
    int t = threadIdx.x;
    int i = blockIdx.x * SCAN_B + t;
    int v = (i < N_NODES) ? g_counts[i] : 0;
    sh[t] = v;
    __syncthreads();
    #pragma unroll
    for (int off = 1; off < SCAN_B; off <<= 1) {
        int a = (t >= off) ? sh[t - off] : 0;
        __syncthreads();
        sh[t] += a;
        __syncthreads();
    }
    if (i < N_NODES) g_rowptr[i] = sh[t] - v;
    if (t == SCAN_B - 1) g_blocksum[blockIdx.x] = sh[t];
}

__global__ void scan_top_kernel() {
    __shared__ int sh[128];
    int t = threadIdx.x;
    int v = (t < SCAN_NBLK) ? g_blocksum[t] : 0;
    sh[t] = v;
    __syncthreads();
    #pragma unroll
    for (int off = 1; off < 128; off <<= 1) {
        int a = (t >= off) ? sh[t - off] : 0;
        __syncthreads();
        sh[t] += a;
        __syncthreads();
    }
    if (t < SCAN_NBLK) g_blockoff[t] = sh[t] - v;
}

__global__ void scan_add_kernel(int E) {
    int i = blockIdx.x * blockDim.x + threadIdx.x;
    if (i < N_NODES) {
        int r = g_rowptr[i] + g_blockoff[i >> 10];
        g_rowptr[i] = r;
        g_pos[i] = r;
    }
    if (i == 0) g_rowptr[N_NODES] = E;
}

__global__ void fill_kernel(const int* __restrict__ src, const int* __restrict__ dst,
                            const float* __restrict__ ew, int E) {
    int e = blockIdx.x * blockDim.x + threadIdx.x;
    if (e >= E) return;
    int p = atomicAdd(&g_pos[dst[e]], 1);
    g_csr_edge[p] = make_int2(src[e], __float_as_int(ew[e]));
}

// ---------------- GEMM1 (mma.sync bf16 x3 split): g_sup1 = x @ W1 --------------
// Block 256 thr / 8 warps, tile 128 rows x 40 cols, BK=32.
// A smem [row][k] (80B rows); B smem K-MAJOR [k][n] == W1 layout (contiguous
// fill, float2 LDG + packed STS.32, conflict-free), frags via ldmatrix.trans.
// Smem double-buffered, one sync/chunk: LDG(c+1) -> MMA(c) -> STS(c+1) -> sync.
__global__ void __launch_bounds__(256) gemm1_mma_kernel(
    const float* __restrict__ x, const float* __restrict__ W1)
{
    __shared__ __align__(16) uint16_t sAhi[2][M_TILE * ASTRIDE];
    __shared__ __align__(16) uint16_t sAlo[2][M_TILE * ASTRIDE];
    __shared__ __align__(16) uint16_t sBhi[2][BK * NHID];     // [k][n], 1280
    __shared__ __align__(16) uint16_t sBlo[2][BK * NHID];

    const int tid  = threadIdx.x;
    const int wid  = tid >> 5;          // 0..7
    const int lane = tid & 31;
    const int row0 = blockIdx.x * M_TILE;

    float acc[5][4];
    #pragma unroll
    for (int ni = 0; ni < 5; ni++)
        #pragma unroll
        for (int q = 0; q < 4; q++) acc[ni][q] = 0.0f;

    const int g  = lane >> 3;            // 0..3 matrix id
    const int rr = lane & 7;
    // A x4 frag: rows wid*16 + (g&1)*8 + rr, k-half (g>>1)*8
    const uint32_t aOff =
        (uint32_t)(((wid * 16 + (g & 1) * 8 + rr) * ASTRIDE + (g >> 1) * 8) * 2);
    // B trans frags from [k][n]: matrix m covers k-octet (m&1), n-octet base+(m>>1)
    uint32_t bOff4[2];
    #pragma unroll
    for (int p = 0; p < 2; p++)
        bOff4[p] = (uint32_t)((((g & 1) * 8 + rr) * NHID + (2 * p + (g >> 1)) * 8) * 2);
    const uint32_t bOff2 =
        (uint32_t)((((g & 1) * 8 + rr) * NHID + 32) * 2);   // ni=4 (lanes 0-15: g=0,1)

    float  pa[16];
    float2 pb[3];

    // ---- prefetch chunk 0 (A: lane=k, rows wid+it*8; B: contiguous float2) ----
    {
        const int gk = lane;
        #pragma unroll
        for (int it = 0; it < 16; it++) {
            int gr = row0 + wid + it * 8;
            pa[it] = (gr < N_NODES) ? __ldg(x + (size_t)gr * NFEAT + gk) : 0.0f;
        }
        #pragma unroll
        for (int it = 0; it < 3; it++) {
            int pidx = tid + it * 256;
            pb[it] = (pidx < 640) ? __ldg((const float2*)W1 + pidx) : make_float2(0.f, 0.f);
        }
    }
    // ---- store chunk 0 into buffer 0 ----
    #pragma unroll
    for (int it = 0; it < 16; it++) {
        int r = wid + it * 8;
        uint16_t hi, lo;
        split_bf16(pa[it], hi, lo);
        sAhi[0][r * ASTRIDE + lane] = hi;
        sAlo[0][r * ASTRIDE + lane] = lo;
    }
    #pragma unroll
    for (int it = 0; it < 3; it++) {
        int pidx = tid + it * 256;
        if (pidx < 640) {
            uint16_t h0, l0, h1, l1;
            split_bf16(pb[it].x, h0, l0);
            split_bf16(pb[it].y, h1, l1);
            ((uint32_t*)sBhi[0])[pidx] = (uint32_t)h0 | ((uint32_t)h1 << 16);
            ((uint32_t*)sBlo[0])[pidx] = (uint32_t)l0 | ((uint32_t)l1 << 16);
        }
    }
    __syncthreads();

    for (int c = 0; c < NCHUNK; c++) {
        const int cur = c & 1;
        const bool more = (c + 1 < NCHUNK);

        // ---- LDG chunk c+1 (latency covered by MMAs below) ----
        if (more) {
            const int k0n = (c + 1) * BK;
            const int gk = k0n + lane;
            const bool kok = (gk < NFEAT);
            #pragma unroll
            for (int it = 0; it < 16; it++) {
                int gr = row0 + wid + it * 8;
                pa[it] = (kok && gr < N_NODES) ? __ldg(x + (size_t)gr * NFEAT + gk) : 0.0f;
            }
            const int bbase = k0n * NHID;   // even
            #pragma unroll
            for (int it = 0; it < 3; it++) {
                int pidx = tid + it * 256;
                int ge = bbase + 2 * pidx;
                pb[it] = (pidx < 640 && ge + 1 < W1_TOT)
                       ? __ldg((const float2*)(W1 + ge)) : make_float2(0.f, 0.f);
            }
        }

        // ---- MMAs for chunk c from buf[cur] ----
        const uint32_t aHiB = (uint32_t)__cvta_generic_to_shared(sAhi[cur]);
        const uint32_t aLoB = (uint32_t)__cvta_generic_to_shared(sAlo[cur]);
        const uint32_t bHiB = (uint32_t)__cvta_generic_to_shared(sBhi[cur]);
        const uint32_t bLoB = (uint32_t)__cvta_generic_to_shared(sBlo[cur]);
        #pragma unroll
        for (int ks = 0; ks < 2; ks++) {
            const uint32_t kbA = (uint32_t)(ks * 16 * 2);          // 16 bf16 = 32B
            const uint32_t kbB = (uint32_t)(ks * 16 * NHID * 2);   // 16 k-rows = 1280B
            uint32_t ahi[4], alo[4], bh[10], bl[10];
            ldsm4 (ahi,    aHiB + aOff + kbA);
            ldsm4 (alo,    aLoB + aOff + kbA);
            ldsm4t(bh + 0, bHiB + bOff4[0] + kbB);   // frags ni=0,1
            ldsm4t(bh + 4, bHiB + bOff4[1] + kbB);   // frags ni=2,3
            ldsm2t(bh + 8, bHiB + bOff2 + kbB);      // frag  ni=4
            ldsm4t(bl + 0, bLoB + bOff4[0] + kbB);
            ldsm4t(bl + 4, bLoB + bOff4[1] + kbB);
            ldsm2t(bl + 8, bLoB + bOff2 + kbB);
            #pragma unroll
            for (int ni = 0; ni < 5; ni++) {
                mma_bf16(acc[ni], ahi, bh + ni * 2);
                mma_bf16(acc[ni], ahi, bl + ni * 2);
                mma_bf16(acc[ni], alo, bh + ni * 2);
            }
        }

        // ---- STS chunk c+1 into buf[cur^1] ----
        if (more) {
            const int nxt = cur ^ 1;
            #pragma unroll
            for (int it = 0; it < 16; it++) {
                int r = wid + it * 8;
                uint16_t hi, lo;
                split_bf16(pa[it], hi, lo);
                sAhi[nxt][r * ASTRIDE + lane] = hi;
                sAlo[nxt][r * ASTRIDE + lane] = lo;
            }
            #pragma unroll
            for (int it = 0; it < 3; it++) {
                int pidx = tid + it * 256;
                if (pidx < 640) {
                    uint16_t h0, l0, h1, l1;
                    split_bf16(pb[it].x, h0, l0);
                    split_bf16(pb[it].y, h1, l1);
                    ((uint32_t*)sBhi[nxt])[pidx] = (uint32_t)h0 | ((uint32_t)h1 << 16);
                    ((uint32_t*)sBlo[nxt])[pidx] = (uint32_t)l0 | ((uint32_t)l1 << 16);
                }
            }
        }
        __syncthreads();
    }

    // ---- writeout: warp w rows w*16 + lane/4 (+8), cols ni*8 + (lane%4)*2 ----
    const int rbase = row0 + wid * 16 + (lane >> 2);
    const int cbase = (lane & 3) * 2;
    #pragma unroll
    for (int ni = 0; ni < 5; ni++) {
        int col = ni * 8 + cbase;
        if (rbase < N_NODES) {
            float2 v = make_float2(acc[ni][0], acc[ni][1]);
            *(float2*)(g_sup1 + (size_t)rbase * NHID + col) = v;
        }
        if (rbase + 8 < N_NODES) {
            float2 v = make_float2(acc[ni][2], acc[ni][3]);
            *(float2*)(g_sup1 + (size_t)(rbase + 8) * NHID + col) = v;
        }
    }
}

// ------- agg1 + bias/relu/dropout + GEMM2 fused (warp per node) ---------------
__global__ void __launch_bounds__(256) agg1_gemm2_kernel(
    const float* __restrict__ b1, const float* __restrict__ mask,
    const float* __restrict__ W2)
{
    __shared__ float w2s[NHID * NCLASS];   // 280, row-major [k][c]
    for (int i = threadIdx.x; i < NHID * NCLASS; i += 256) w2s[i] = W2[i];
    __syncthreads();

    int n = (blockIdx.x * blockDim.x + threadIdx.x) >> 5;
    int lane = threadIdx.x & 31;
    if (n >= N_NODES) return;
    int beg = g_rowptr[n], end = g_rowptr[n + 1];

    float acc0 = 0.0f, acc1 = 0.0f;
    #pragma unroll 1
    for (int e0 = beg; e0 < end; e0 += 4) {
        int2 ed[4];
        #pragma unroll
        for (int j = 0; j < 4; j++) {
            int idx = e0 + j;
            ed[j] = (idx < end) ? __ldg(&g_csr_edge[idx]) : make_int2(0, 0);
        }
        #pragma unroll
        for (int j = 0; j < 4; j++) {
            float w = __int_as_float(ed[j].y);
            const float* row = g_sup1 + (size_t)ed[j].x * NHID;
            acc0 = fmaf(w, __ldg(row + lane), acc0);
            if (lane < 8) acc1 = fmaf(w, __ldg(row + 32 + lane), acc1);
        }
    }
    float h0, h1v = 0.0f;
    {
        float v = fmaxf(acc0 + __ldg(b1 + lane), 0.0f);
        float m = __ldg(mask + (size_t)n * NHID + lane);
        h0 = (m > 0.5f) ? v * 2.0f : 0.0f;
    }
    if (lane < 8) {
        int cidx = 32 + lane;
        float v = fmaxf(acc1 + __ldg(b1 + cidx), 0.0f);
        float m = __ldg(mask + (size_t)n * NHID + cidx);
        h1v = (m > 0.5f) ? v * 2.0f : 0.0f;
    }
    #pragma unroll
    for (int c = 0; c < NCLASS; c++) {
        float p = h0 * w2s[lane * NCLASS + c];
        if (lane < 8) p += h1v * w2s[(32 + lane) * NCLASS + c];
        p += __shfl_xor_sync(0xFFFFFFFFu, p, 16);
        p += __shfl_xor_sync(0xFFFFFFFFu, p, 8);
        p += __shfl_xor_sync(0xFFFFFFFFu, p, 4);
        p += __shfl_xor_sync(0xFFFFFFFFu, p, 2);
        p += __shfl_xor_sync(0xFFFFFFFFu, p, 1);
        if (lane == 0) g_sup2[(size_t)n * NC_PAD + c] = p;
    }
    if (lane == 0) g_sup2[(size_t)n * NC_PAD + NCLASS] = 0.0f;  // pad
}

// ------- agg2 (warp/node, 4 edges x 8 feats) fused with bias + log_softmax ----
__global__ void __launch_bounds__(256) agg2_lsm_kernel(
    const float* __restrict__ b2, float* __restrict__ out)
{
    int n = (blockIdx.x * blockDim.x + threadIdx.x) >> 5;
    int lane = threadIdx.x & 31;
    if (n >= N_NODES) return;
    int beg = g_rowptr[n], end = g_rowptr[n + 1];
    int j = lane >> 3;      // edge sub-slot 0..3
    int f = lane & 7;       // feature 0..7 (7 = pad)

    float acc = 0.0f;
    #pragma unroll 1
    for (int e0 = beg; e0 < end; e0 += 4) {
        int idx = e0 + j;
        int2 ed = (idx < end) ? __ldg(&g_csr_edge[idx]) : make_int2(0, 0);
        float w = __int_as_float(ed.y);
        acc = fmaf(w, __ldg(g_sup2 + (size_t)ed.x * NC_PAD + f), acc);
    }
    acc += __shfl_xor_sync(0xFFFFFFFFu, acc, 8);
    acc += __shfl_xor_sync(0xFFFFFFFFu, acc, 16);

    float z = acc + __ldg(b2 + ((f < NCLASS) ? f : 0));
    float m = (f < NCLASS) ? z : -1e30f;
    m = fmaxf(m, __shfl_xor_sync(0xFFFFFFFFu, m, 1));
    m = fmaxf(m, __shfl_xor_sync(0xFFFFFFFFu, m, 2));
    m = fmaxf(m, __shfl_xor_sync(0xFFFFFFFFu, m, 4));
    float ex = (f < NCLASS) ? __expf(z - m) : 0.0f;
    float s = ex;
    s += __shfl_xor_sync(0xFFFFFFFFu, s, 1);
    s += __shfl_xor_sync(0xFFFFFFFFu, s, 2);
    s += __shfl_xor_sync(0xFFFFFFFFu, s, 4);
    float lse = m + __logf(s);
    if (f < NCLASS && j == 0)
        out[(size_t)n * NCLASS + f] = z - lse;
}

// ---------------- launch -----------------------------------------------------
extern "C" void kernel_launch(void* const* d_in, const int* in_sizes, int n_in,
                              void* d_out, int out_size)
{
    const float* x    = (const float*)d_in[0];
    const int*   src  = (const int*)  d_in[1];
    const int*   dst  = (const int*)  d_in[2];
    const float* ew   = (const float*)d_in[3];
    const float* W1   = (const float*)d_in[4];
    const float* b1   = (const float*)d_in[5];
    const float* W2   = (const float*)d_in[6];
    const float* b2   = (const float*)d_in[7];
    const float* mask = (const float*)d_in[8];
    float* out = (float*)d_out;

    const int E = in_sizes[1];
    const int NBLK_M = (N_NODES + M_TILE - 1) / M_TILE;   // 782

    // gemm1 stays at launch index 3 (captured by ncu -s/-c).             idx
    clear_counts_kernel<<<(N_NODES + 255) / 256, 256>>>();              //  0
    hist_kernel<<<(E + 255) / 256, 256>>>(dst, E);                      //  1
    scan_part_kernel<<<SCAN_NBLK, SCAN_B>>>();                          //  2
    gemm1_mma_kernel<<<NBLK_M, 256>>>(x, W1);                           //  3  <- profiled
    scan_top_kernel<<<1, 128>>>();                                      //  4
    scan_add_kernel<<<(N_NODES + 255) / 256, 256>>>(E);                 //  5
    fill_kernel<<<(E + 255) / 256, 256>>>(src, dst, ew, E);             //  6
    agg1_gemm2_kernel<<<(N_NODES * 32 + 255) / 256, 256>>>(b1, mask, W2); // 7
    agg2_lsm_kernel<<<(N_NODES * 32 + 255) / 256, 256>>>(b2, out);      //  8
}

// round 13
// speedup vs baseline: 1.2094x; 1.0453x over previous
#include <cuda_runtime.h>
#include <cuda_bf16.h>
#include <cstdint>

#define N_NODES 100000
#define NFEAT   1433
#define NHID    40
#define NCLASS  7
#define NC_PAD  8
#define E_MAX   3200000
#define SCAN_B  1024
#define SCAN_NBLK ((N_NODES + SCAN_B - 1) / SCAN_B)   // 98

#define M_TILE  128
#define BK      32
#define NCHUNK  ((NFEAT + BK - 1) / BK)   // 45
#define ASTRIDE 40                         // A smem: bf16 elems per row (80B, 16B-mult)
#define W1_TOT  (NFEAT * NHID)             // 57320

// ---------------- scratch (device globals; no allocation allowed) -------------
__device__ float g_sup1[N_NODES * NHID];     // x @ W1 (pre-aggregation)
__device__ float g_sup2[N_NODES * NC_PAD];   // h @ W2 (padded to 8)
__device__ int   g_counts[N_NODES];
__device__ int   g_rowptr[N_NODES + 1];
__device__ int   g_pos[N_NODES];
__device__ int   g_blocksum[SCAN_NBLK];
__device__ int   g_blockoff[SCAN_NBLK];
__device__ int2  g_csr_edge[E_MAX];          // (src, weight-bits) grouped by dst

// ---------------- PTX helpers -------------------------------------------------
__device__ __forceinline__ void ldsm4(uint32_t* r, uint32_t addr) {
    asm volatile("ldmatrix.sync.aligned.m8n8.x4.shared.b16 {%0,%1,%2,%3}, [%4];"
        : "=r"(r[0]), "=r"(r[1]), "=r"(r[2]), "=r"(r[3]) : "r"(addr));
}
__device__ __forceinline__ void ldsm4t(uint32_t* r, uint32_t addr) {
    asm volatile("ldmatrix.sync.aligned.m8n8.x4.trans.shared.b16 {%0,%1,%2,%3}, [%4];"
        : "=r"(r[0]), "=r"(r[1]), "=r"(r[2]), "=r"(r[3]) : "r"(addr));
}
__device__ __forceinline__ void ldsm2t(uint32_t* r, uint32_t addr) {
    asm volatile("ldmatrix.sync.aligned.m8n8.x2.trans.shared.b16 {%0,%1}, [%2];"
        : "=r"(r[0]), "=r"(r[1]) : "r"(addr));
}
__device__ __forceinline__ void mma_bf16(float* d, const uint32_t* a, const uint32_t* b) {
    asm volatile(
        "mma.sync.aligned.m16n8k16.row.col.f32.bf16.bf16.f32 "
        "{%0,%1,%2,%3}, {%4,%5,%6,%7}, {%8,%9}, {%0,%1,%2,%3};"
        : "+f"(d[0]), "+f"(d[1]), "+f"(d[2]), "+f"(d[3])
        : "r"(a[0]), "r"(a[1]), "r"(a[2]), "r"(a[3]), "r"(b[0]), "r"(b[1]));
}

// hi = upper-16-bit truncation (exact bf16 bits); lo = bf16(v - hi).
__device__ __forceinline__ void split_bf16(float v, uint16_t& hi, uint16_t& lo) {
    uint32_t bits = __float_as_uint(v);
    uint32_t hib  = bits & 0xFFFF0000u;
    hi = (uint16_t)(bits >> 16);
    float rem = v - __uint_as_float(hib);
    __nv_bfloat16 lb = __float2bfloat16(rem);
    lo = *reinterpret_cast<uint16_t*>(&lb);
}

// ---------------- CSR build ---------------------------------------------------
__global__ void clear_counts_kernel() {
    int i = blockIdx.x * blockDim.x + threadIdx.x;
    if (i < N_NODES) g_counts[i] = 0;
}

__global__ void hist_kernel(const int* __restrict__ dst, int E) {
    int e = blockIdx.x * blockDim.x + threadIdx.x;
    if (e < E) atomicAdd(&g_counts[dst[e]], 1);
}

__global__ void __launch_bounds__(SCAN_B) scan_part_kernel() {
    __shared__ int sh[SCAN_B];
    int t = threadIdx.x;
    int i = blockIdx.x * SCAN_B + t;
    int v = (i < N_NODES) ? g_counts[i] : 0;
    sh[t] = v;
    __syncthreads();
    #pragma unroll
    for (int off = 1; off < SCAN_B; off <<= 1) {
        int a = (t >= off) ? sh[t - off] : 0;
        __syncthreads();
        sh[t] += a;
        __syncthreads();
    }
    if (i < N_NODES) g_rowptr[i] = sh[t] - v;
    if (t == SCAN_B - 1) g_blocksum[blockIdx.x] = sh[t];
}

__global__ void scan_top_kernel() {
    __shared__ int sh[128];
    int t = threadIdx.x;
    int v = (t < SCAN_NBLK) ? g_blocksum[t] : 0;
    sh[t] = v;
    __syncthreads();
    #pragma unroll
    for (int off = 1; off < 128; off <<= 1) {
        int a = (t >= off) ? sh[t - off] : 0;
        __syncthreads();
        sh[t] += a;
        __syncthreads();
    }
    if (t < SCAN_NBLK) g_blockoff[t] = sh[t] - v;
}

__global__ void scan_add_kernel(int E) {
    int i = blockIdx.x * blockDim.x + threadIdx.x;
    if (i < N_NODES) {
        int r = g_rowptr[i] + g_blockoff[i >> 10];
        g_rowptr[i] = r;
        g_pos[i] = r;
    }
    if (i == 0) g_rowptr[N_NODES] = E;
}

__global__ void fill_kernel(const int* __restrict__ src, const int* __restrict__ dst,
                            const float* __restrict__ ew, int E) {
    int e = blockIdx.x * blockDim.x + threadIdx.x;
    if (e >= E) return;
    int p = atomicAdd(&g_pos[dst[e]], 1);
    g_csr_edge[p] = make_int2(src[e], __float_as_int(ew[e]));
}

// ---------------- GEMM1 (mma.sync bf16 x3 split): g_sup1 = x @ W1 --------------
// Block 128 thr / 4 warps, tile 128 rows x 40 cols, BK=32.
// Warp owns m32 (2 m16 frags) x n40: B-fragment LDSMs amortized over 2x MMAs.
// A smem [row][k]; B smem K-major [k][n] (contiguous fill). Double-buffered,
// one sync/chunk: LDG(c+1) -> MMA(c) -> STS(c+1) -> sync.
__global__ void __launch_bounds__(128) gemm1_mma_kernel(
    const float* __restrict__ x, const float* __restrict__ W1)
{
    __shared__ __align__(16) uint16_t sAhi[2][M_TILE * ASTRIDE];
    __shared__ __align__(16) uint16_t sAlo[2][M_TILE * ASTRIDE];
    __shared__ __align__(16) uint16_t sBhi[2][BK * NHID];     // [k][n], 1280
    __shared__ __align__(16) uint16_t sBlo[2][BK * NHID];

    const int tid  = threadIdx.x;
    const int wid  = tid >> 5;          // 0..3
    const int lane = tid & 31;
    const int row0 = blockIdx.x * M_TILE;

    float acc[2][5][4];
    #pragma unroll
    for (int mi = 0; mi < 2; mi++)
        #pragma unroll
        for (int ni = 0; ni < 5; ni++)
            #pragma unroll
            for (int q = 0; q < 4; q++) acc[mi][ni][q] = 0.0f;

    const int g  = lane >> 3;            // 0..3 matrix id
    const int rr = lane & 7;
    // A x4 frags (mi): rows wid*32 + mi*16 + (g&1)*8 + rr, k-half (g>>1)*8
    uint32_t aOff[2];
    #pragma unroll
    for (int mi = 0; mi < 2; mi++)
        aOff[mi] = (uint32_t)(((wid * 32 + mi * 16 + (g & 1) * 8 + rr) * ASTRIDE
                               + (g >> 1) * 8) * 2);
    // B trans frags from [k][n]: matrix g covers k-octet (g&1), n-octet 2p+(g>>1)
    uint32_t bOff4[2];
    #pragma unroll
    for (int p = 0; p < 2; p++)
        bOff4[p] = (uint32_t)((((g & 1) * 8 + rr) * NHID + (2 * p + (g >> 1)) * 8) * 2);
    const uint32_t bOff2 =
        (uint32_t)((((g & 1) * 8 + rr) * NHID + 32) * 2);   // ni=4 (lanes 0-15)

    float  pa[32];   // A prefetch: rows wid + it*4, lane = k
    float2 pb[5];    // B prefetch: pidx = tid + it*128, contiguous float2

    // ---- prefetch chunk 0 ----
    {
        const int gk = lane;
        #pragma unroll
        for (int it = 0; it < 32; it++) {
            int gr = row0 + wid + it * 4;
            pa[it] = (gr < N_NODES) ? __ldg(x + (size_t)gr * NFEAT + gk) : 0.0f;
        }
        #pragma unroll
        for (int it = 0; it < 5; it++) {
            int pidx = tid + it * 128;   // < 640
            pb[it] = __ldg((const float2*)W1 + pidx);
        }
    }
    // ---- store chunk 0 into buffer 0 ----
    #pragma unroll
    for (int it = 0; it < 32; it++) {
        int r = wid + it * 4;
        uint16_t hi, lo;
        split_bf16(pa[it], hi, lo);
        sAhi[0][r * ASTRIDE + lane] = hi;
        sAlo[0][r * ASTRIDE + lane] = lo;
    }
    #pragma unroll
    for (int it = 0; it < 5; it++) {
        int pidx = tid + it * 128;
        uint16_t h0, l0, h1, l1;
        split_bf16(pb[it].x, h0, l0);
        split_bf16(pb[it].y, h1, l1);
        ((uint32_t*)sBhi[0])[pidx] = (uint32_t)h0 | ((uint32_t)h1 << 16);
        ((uint32_t*)sBlo[0])[pidx] = (uint32_t)l0 | ((uint32_t)l1 << 16);
    }
    __syncthreads();

    for (int c = 0; c < NCHUNK; c++) {
        const int cur = c & 1;
        const bool more = (c + 1 < NCHUNK);

        // ---- LDG chunk c+1 (latency covered by MMAs below) ----
        if (more) {
            const int k0n = (c + 1) * BK;
            const int gk = k0n + lane;
            const bool kok = (gk < NFEAT);
            #pragma unroll
            for (int it = 0; it < 32; it++) {
                int gr = row0 + wid + it * 4;
                pa[it] = (kok && gr < N_NODES) ? __ldg(x + (size_t)gr * NFEAT + gk) : 0.0f;
            }
            const int bbase = k0n * NHID;   // even
            #pragma unroll
            for (int it = 0; it < 5; it++) {
                int pidx = tid + it * 128;
                int ge = bbase + 2 * pidx;
                pb[it] = (ge + 1 < W1_TOT) ? __ldg((const float2*)(W1 + ge))
                                           : make_float2(0.f, 0.f);
            }
        }

        // ---- MMAs for chunk c from buf[cur] ----
        const uint32_t aHiB = (uint32_t)__cvta_generic_to_shared(sAhi[cur]);
        const uint32_t aLoB = (uint32_t)__cvta_generic_to_shared(sAlo[cur]);
        const uint32_t bHiB = (uint32_t)__cvta_generic_to_shared(sBhi[cur]);
        const uint32_t bLoB = (uint32_t)__cvta_generic_to_shared(sBlo[cur]);
        #pragma unroll
        for (int ks = 0; ks < 2; ks++) {
            const uint32_t kbA = (uint32_t)(ks * 16 * 2);          // 16 bf16 = 32B
            const uint32_t kbB = (uint32_t)(ks * 16 * NHID * 2);   // 16 k-rows
            uint32_t ahi[2][4], alo[2][4], bh[10], bl[10];
            ldsm4 (ahi[0], aHiB + aOff[0] + kbA);
            ldsm4 (ahi[1], aHiB + aOff[1] + kbA);
            ldsm4 (alo[0], aLoB + aOff[0] + kbA);
            ldsm4 (alo[1], aLoB + aOff[1] + kbA);
            ldsm4t(bh + 0, bHiB + bOff4[0] + kbB);   // frags ni=0,1
            ldsm4t(bh + 4, bHiB + bOff4[1] + kbB);   // frags ni=2,3
            ldsm2t(bh + 8, bHiB + bOff2 + kbB);      // frag  ni=4
            ldsm4t(bl + 0, bLoB + bOff4[0] + kbB);
            ldsm4t(bl + 4, bLoB + bOff4[1] + kbB);
            ldsm2t(bl + 8, bLoB + bOff2 + kbB);
            #pragma unroll
            for (int mi = 0; mi < 2; mi++)
                #pragma unroll
                for (int ni = 0; ni < 5; ni++) {
                    mma_bf16(acc[mi][ni], ahi[mi], bh + ni * 2);
                    mma_bf16(acc[mi][ni], ahi[mi], bl + ni * 2);
                    mma_bf16(acc[mi][ni], alo[mi], bh + ni * 2);
                }
        }

        // ---- STS chunk c+1 into buf[cur^1] ----
        if (more) {
            const int nxt = cur ^ 1;
            #pragma unroll
            for (int it = 0; it < 32; it++) {
                int r = wid + it * 4;
                uint16_t hi, lo;
                split_bf16(pa[it], hi, lo);
                sAhi[nxt][r * ASTRIDE + lane] = hi;
                sAlo[nxt][r * ASTRIDE + lane] = lo;
            }
            #pragma unroll
            for (int it = 0; it < 5; it++) {
                int pidx = tid + it * 128;
                uint16_t h0, l0, h1, l1;
                split_bf16(pb[it].x, h0, l0);
                split_bf16(pb[it].y, h1, l1);
                ((uint32_t*)sBhi[nxt])[pidx] = (uint32_t)h0 | ((uint32_t)h1 << 16);
                ((uint32_t*)sBlo[nxt])[pidx] = (uint32_t)l0 | ((uint32_t)l1 << 16);
            }
        }
        __syncthreads();
    }

    // ---- writeout: warp w rows w*32 + mi*16 + lane/4 (+8), cols ni*8+(lane%4)*2
    const int cbase = (lane & 3) * 2;
    #pragma unroll
    for (int mi = 0; mi < 2; mi++) {
        const int rbase = row0 + wid * 32 + mi * 16 + (lane >> 2);
        #pragma unroll
        for (int ni = 0; ni < 5; ni++) {
            int col = ni * 8 + cbase;
            if (rbase < N_NODES) {
                float2 v = make_float2(acc[mi][ni][0], acc[mi][ni][1]);
                *(float2*)(g_sup1 + (size_t)rbase * NHID + col) = v;
            }
            if (rbase + 8 < N_NODES) {
                float2 v = make_float2(acc[mi][ni][2], acc[mi][ni][3]);
                *(float2*)(g_sup1 + (size_t)(rbase + 8) * NHID + col) = v;
            }
        }
    }
}

// ------- agg1 + bias/relu/dropout + GEMM2 fused (warp per node) ---------------
__global__ void __launch_bounds__(256) agg1_gemm2_kernel(
    const float* __restrict__ b1, const float* __restrict__ mask,
    const float* __restrict__ W2)
{
    __shared__ float w2s[NHID * NCLASS];   // 280, row-major [k][c]
    for (int i = threadIdx.x; i < NHID * NCLASS; i += 256) w2s[i] = W2[i];
    __syncthreads();

    int n = (blockIdx.x * blockDim.x + threadIdx.x) >> 5;
    int lane = threadIdx.x & 31;
    if (n >= N_NODES) return;
    int beg = g_rowptr[n], end = g_rowptr[n + 1];

    float acc0 = 0.0f, acc1 = 0.0f;
    #pragma unroll 1
    for (int e0 = beg; e0 < end; e0 += 4) {
        int2 ed[4];
        #pragma unroll
        for (int j = 0; j < 4; j++) {
            int idx = e0 + j;
            ed[j] = (idx < end) ? __ldg(&g_csr_edge[idx]) : make_int2(0, 0);
        }
        #pragma unroll
        for (int j = 0; j < 4; j++) {
            float w = __int_as_float(ed[j].y);
            const float* row = g_sup1 + (size_t)ed[j].x * NHID;
            acc0 = fmaf(w, __ldg(row + lane), acc0);
            if (lane < 8) acc1 = fmaf(w, __ldg(row + 32 + lane), acc1);
        }
    }
    float h0, h1v = 0.0f;
    {
        float v = fmaxf(acc0 + __ldg(b1 + lane), 0.0f);
        float m = __ldg(mask + (size_t)n * NHID + lane);
        h0 = (m > 0.5f) ? v * 2.0f : 0.0f;
    }
    if (lane < 8) {
        int cidx = 32 + lane;
        float v = fmaxf(acc1 + __ldg(b1 + cidx), 0.0f);
        float m = __ldg(mask + (size_t)n * NHID + cidx);
        h1v = (m > 0.5f) ? v * 2.0f : 0.0f;
    }
    #pragma unroll
    for (int c = 0; c < NCLASS; c++) {
        float p = h0 * w2s[lane * NCLASS + c];
        if (lane < 8) p += h1v * w2s[(32 + lane) * NCLASS + c];
        p += __shfl_xor_sync(0xFFFFFFFFu, p, 16);
        p += __shfl_xor_sync(0xFFFFFFFFu, p, 8);
        p += __shfl_xor_sync(0xFFFFFFFFu, p, 4);
        p += __shfl_xor_sync(0xFFFFFFFFu, p, 2);
        p += __shfl_xor_sync(0xFFFFFFFFu, p, 1);
        if (lane == 0) g_sup2[(size_t)n * NC_PAD + c] = p;
    }
    if (lane == 0) g_sup2[(size_t)n * NC_PAD + NCLASS] = 0.0f;  // pad
}

// ------- agg2 (warp/node, 4 edges x 8 feats) fused with bias + log_softmax ----
__global__ void __launch_bounds__(256) agg2_lsm_kernel(
    const float* __restrict__ b2, float* __restrict__ out)
{
    int n = (blockIdx.x * blockDim.x + threadIdx.x) >> 5;
    int lane = threadIdx.x & 31;
    if (n >= N_NODES) return;
    int beg = g_rowptr[n], end = g_rowptr[n + 1];
    int j = lane >> 3;      // edge sub-slot 0..3
    int f = lane & 7;       // feature 0..7 (7 = pad)

    float acc = 0.0f;
    #pragma unroll 1
    for (int e0 = beg; e0 < end; e0 += 4) {
        int idx = e0 + j;
        int2 ed = (idx < end) ? __ldg(&g_csr_edge[idx]) : make_int2(0, 0);
        float w = __int_as_float(ed.y);
        acc = fmaf(w, __ldg(g_sup2 + (size_t)ed.x * NC_PAD + f), acc);
    }
    acc += __shfl_xor_sync(0xFFFFFFFFu, acc, 8);
    acc += __shfl_xor_sync(0xFFFFFFFFu, acc, 16);

    float z = acc + __ldg(b2 + ((f < NCLASS) ? f : 0));
    float m = (f < NCLASS) ? z : -1e30f;
    m = fmaxf(m, __shfl_xor_sync(0xFFFFFFFFu, m, 1));
    m = fmaxf(m, __shfl_xor_sync(0xFFFFFFFFu, m, 2));
    m = fmaxf(m, __shfl_xor_sync(0xFFFFFFFFu, m, 4));
    float ex = (f < NCLASS) ? __expf(z - m) : 0.0f;
    float s = ex;
    s += __shfl_xor_sync(0xFFFFFFFFu, s, 1);
    s += __shfl_xor_sync(0xFFFFFFFFu, s, 2);
    s += __shfl_xor_sync(0xFFFFFFFFu, s, 4);
    float lse = m + __logf(s);
    if (f < NCLASS && j == 0)
        out[(size_t)n * NCLASS + f] = z - lse;
}

// ---------------- launch -----------------------------------------------------
extern "C" void kernel_launch(void* const* d_in, const int* in_sizes, int n_in,
                              void* d_out, int out_size)
{
    const float* x    = (const float*)d_in[0];
    const int*   src  = (const int*)  d_in[1];
    const int*   dst  = (const int*)  d_in[2];
    const float* ew   = (const float*)d_in[3];
    const float* W1   = (const float*)d_in[4];
    const float* b1   = (const float*)d_in[5];
    const float* W2   = (const float*)d_in[6];
    const float* b2   = (const float*)d_in[7];
    const float* mask = (const float*)d_in[8];
    float* out = (float*)d_out;

    const int E = in_sizes[1];
    const int NBLK_M = (N_NODES + M_TILE - 1) / M_TILE;   // 782

    // gemm1 stays at launch index 3 (captured by ncu -s/-c).             idx
    clear_counts_kernel<<<(N_NODES + 255) / 256, 256>>>();              //  0
    hist_kernel<<<(E + 255) / 256, 256>>>(dst, E);                      //  1
    scan_part_kernel<<<SCAN_NBLK, SCAN_B>>>();                          //  2
    gemm1_mma_kernel<<<NBLK_M, 128>>>(x, W1);                           //  3  <- profiled
    scan_top_kernel<<<1, 128>>>();                                      //  4
    scan_add_kernel<<<(N_NODES + 255) / 256, 256>>>(E);                 //  5
    fill_kernel<<<(E + 255) / 256, 256>>>(src, dst, ew, E);             //  6
    agg1_gemm2_kernel<<<(N_NODES * 32 + 255) / 256, 256>>>(b1, mask, W2); // 7
    agg2_lsm_kernel<<<(N_NODES * 32 + 255) / 256, 256>>>(b2, out);      //  8
}

// round 14
// speedup vs baseline: 1.3056x; 1.0796x over previous
#include <cuda_runtime.h>
#include <cuda_bf16.h>
#include <cstdint>

#define N_NODES 100000
#define NFEAT   1433
#define NHID    40
#define NCLASS  7
#define NC_PAD  8
#define E_MAX   3200000
#define SCAN_B  1024
#define SCAN_NBLK ((N_NODES + SCAN_B - 1) / SCAN_B)   // 98

#define M_TILE  128
#define BK      32
#define NCHUNK  ((NFEAT + BK - 1) / BK)   // 45
#define ASTRIDE 40                         // A smem: bf16 elems per row (80B, 16B-mult)
#define W1_TOT  (NFEAT * NHID)             // 57320

// ---------------- scratch (device globals; no allocation allowed) -------------
__device__ float g_sup1[N_NODES * NHID];     // x @ W1 (pre-aggregation)
__device__ float g_sup2[N_NODES * NC_PAD];   // h @ W2 (padded to 8)
__device__ int   g_counts[N_NODES];
__device__ int   g_rowptr[N_NODES + 1];
__device__ int   g_pos[N_NODES];
__device__ int   g_blocksum[SCAN_NBLK];
__device__ int   g_blockoff[SCAN_NBLK];
__device__ int2  g_csr_edge[E_MAX];          // (src, weight-bits) grouped by dst

// ---------------- PTX helpers -------------------------------------------------
__device__ __forceinline__ void ldsm4(uint32_t* r, uint32_t addr) {
    asm volatile("ldmatrix.sync.aligned.m8n8.x4.shared.b16 {%0,%1,%2,%3}, [%4];"
        : "=r"(r[0]), "=r"(r[1]), "=r"(r[2]), "=r"(r[3]) : "r"(addr));
}
__device__ __forceinline__ void ldsm4t(uint32_t* r, uint32_t addr) {
    asm volatile("ldmatrix.sync.aligned.m8n8.x4.trans.shared.b16 {%0,%1,%2,%3}, [%4];"
        : "=r"(r[0]), "=r"(r[1]), "=r"(r[2]), "=r"(r[3]) : "r"(addr));
}
__device__ __forceinline__ void ldsm2t(uint32_t* r, uint32_t addr) {
    asm volatile("ldmatrix.sync.aligned.m8n8.x2.trans.shared.b16 {%0,%1}, [%2];"
        : "=r"(r[0]), "=r"(r[1]) : "r"(addr));
}
__device__ __forceinline__ void mma_bf16(float* d, const uint32_t* a, const uint32_t* b) {
    asm volatile(
        "mma.sync.aligned.m16n8k16.row.col.f32.bf16.bf16.f32 "
        "{%0,%1,%2,%3}, {%4,%5,%6,%7}, {%8,%9}, {%0,%1,%2,%3};"
        : "+f"(d[0]), "+f"(d[1]), "+f"(d[2]), "+f"(d[3])
        : "r"(a[0]), "r"(a[1]), "r"(a[2]), "r"(a[3]), "r"(b[0]), "r"(b[1]));
}

// hi = upper-16-bit truncation (exact bf16 bits); lo = bf16(v - hi).
__device__ __forceinline__ void split_bf16(float v, uint16_t& hi, uint16_t& lo) {
    uint32_t bits = __float_as_uint(v);
    uint32_t hib  = bits & 0xFFFF0000u;
    hi = (uint16_t)(bits >> 16);
    float rem = v - __uint_as_float(hib);
    __nv_bfloat16 lb = __float2bfloat16(rem);
    lo = *reinterpret_cast<uint16_t*>(&lb);
}

// ---------------- CSR build ---------------------------------------------------
__global__ void clear_counts_kernel() {
    int i = blockIdx.x * blockDim.x + threadIdx.x;
    if (i < N_NODES) g_counts[i] = 0;
}

__global__ void hist_kernel(const int* __restrict__ dst, int E) {
    int e = blockIdx.x * blockDim.x + threadIdx.x;
    if (e < E) atomicAdd(&g_counts[dst[e]], 1);
}

__global__ void __launch_bounds__(SCAN_B) scan_part_kernel() {
    __shared__ int sh[SCAN_B];
    int t = threadIdx.x;
    int i = blockIdx.x * SCAN_B + t;
    int v = (i < N_NODES) ? g_counts[i] : 0;
    sh[t] = v;
    __syncthreads();
    #pragma unroll
    for (int off = 1; off < SCAN_B; off <<= 1) {
        int a = (t >= off) ? sh[t - off] : 0;
        __syncthreads();
        sh[t] += a;
        __syncthreads();
    }
    if (i < N_NODES) g_rowptr[i] = sh[t] - v;
    if (t == SCAN_B - 1) g_blocksum[blockIdx.x] = sh[t];
}

__global__ void scan_top_kernel() {
    __shared__ int sh[128];
    int t = threadIdx.x;
    int v = (t < SCAN_NBLK) ? g_blocksum[t] : 0;
    sh[t] = v;
    __syncthreads();
    #pragma unroll
    for (int off = 1; off < 128; off <<= 1) {
        int a = (t >= off) ? sh[t - off] : 0;
        __syncthreads();
        sh[t] += a;
        __syncthreads();
    }
    if (t < SCAN_NBLK) g_blockoff[t] = sh[t] - v;
}

__global__ void scan_add_kernel(int E) {
    int i = blockIdx.x * blockDim.x + threadIdx.x;
    if (i < N_NODES) {
        int r = g_rowptr[i] + g_blockoff[i >> 10];
        g_rowptr[i] = r;
        g_pos[i] = r;
    }
    if (i == 0) g_rowptr[N_NODES] = E;
}

__global__ void fill_kernel(const int* __restrict__ src, const int* __restrict__ dst,
                            const float* __restrict__ ew, int E) {
    int e = blockIdx.x * blockDim.x + threadIdx.x;
    if (e >= E) return;
    int p = atomicAdd(&g_pos[dst[e]], 1);
    g_csr_edge[p] = make_int2(src[e], __float_as_int(ew[e]));
}

// ---------------- GEMM1 (mma.sync bf16 x3 split): g_sup1 = x @ W1 --------------
// Block 128 thr / 4 warps, tile 128 rows x 40 cols, BK=32, warp owns m32 x n40.
// A smem [row][k]; B smem K-major [k][n]. Double-buffered, one sync/chunk.
__global__ void __launch_bounds__(128) gemm1_mma_kernel(
    const float* __restrict__ x, const float* __restrict__ W1)
{
    __shared__ __align__(16) uint16_t sAhi[2][M_TILE * ASTRIDE];
    __shared__ __align__(16) uint16_t sAlo[2][M_TILE * ASTRIDE];
    __shared__ __align__(16) uint16_t sBhi[2][BK * NHID];     // [k][n], 1280
    __shared__ __align__(16) uint16_t sBlo[2][BK * NHID];

    const int tid  = threadIdx.x;
    const int wid  = tid >> 5;          // 0..3
    const int lane = tid & 31;
    const int row0 = blockIdx.x * M_TILE;

    float acc[2][5][4];
    #pragma unroll
    for (int mi = 0; mi < 2; mi++)
        #pragma unroll
        for (int ni = 0; ni < 5; ni++)
            #pragma unroll
            for (int q = 0; q < 4; q++) acc[mi][ni][q] = 0.0f;

    const int g  = lane >> 3;            // 0..3 matrix id
    const int rr = lane & 7;
    uint32_t aOff[2];
    #pragma unroll
    for (int mi = 0; mi < 2; mi++)
        aOff[mi] = (uint32_t)(((wid * 32 + mi * 16 + (g & 1) * 8 + rr) * ASTRIDE
                               + (g >> 1) * 8) * 2);
    uint32_t bOff4[2];
    #pragma unroll
    for (int p = 0; p < 2; p++)
        bOff4[p] = (uint32_t)((((g & 1) * 8 + rr) * NHID + (2 * p + (g >> 1)) * 8) * 2);
    const uint32_t bOff2 =
        (uint32_t)((((g & 1) * 8 + rr) * NHID + 32) * 2);   // ni=4 (lanes 0-15)

    float  pa[32];   // A prefetch: rows wid + it*4, lane = k
    float2 pb[5];    // B prefetch: pidx = tid + it*128, contiguous float2

    // ---- prefetch chunk 0 ----
    {
        const int gk = lane;
        #pragma unroll
        for (int it = 0; it < 32; it++) {
            int gr = row0 + wid + it * 4;
            pa[it] = (gr < N_NODES) ? __ldg(x + (size_t)gr * NFEAT + gk) : 0.0f;
        }
        #pragma unroll
        for (int it = 0; it < 5; it++) {
            int pidx = tid + it * 128;   // < 640
            pb[it] = __ldg((const float2*)W1 + pidx);
        }
    }
    // ---- store chunk 0 into buffer 0 ----
    #pragma unroll
    for (int it = 0; it < 32; it++) {
        int r = wid + it * 4;
        uint16_t hi, lo;
        split_bf16(pa[it], hi, lo);
        sAhi[0][r * ASTRIDE + lane] = hi;
        sAlo[0][r * ASTRIDE + lane] = lo;
    }
    #pragma unroll
    for (int it = 0; it < 5; it++) {
        int pidx = tid + it * 128;
        uint16_t h0, l0, h1, l1;
        split_bf16(pb[it].x, h0, l0);
        split_bf16(pb[it].y, h1, l1);
        ((uint32_t*)sBhi[0])[pidx] = (uint32_t)h0 | ((uint32_t)h1 << 16);
        ((uint32_t*)sBlo[0])[pidx] = (uint32_t)l0 | ((uint32_t)l1 << 16);
    }
    __syncthreads();

    for (int c = 0; c < NCHUNK; c++) {
        const int cur = c & 1;
        const bool more = (c + 1 < NCHUNK);

        if (more) {
            const int k0n = (c + 1) * BK;
            const int gk = k0n + lane;
            const bool kok = (gk < NFEAT);
            #pragma unroll
            for (int it = 0; it < 32; it++) {
                int gr = row0 + wid + it * 4;
                pa[it] = (kok && gr < N_NODES) ? __ldg(x + (size_t)gr * NFEAT + gk) : 0.0f;
            }
            const int bbase = k0n * NHID;   // even
            #pragma unroll
            for (int it = 0; it < 5; it++) {
                int pidx = tid + it * 128;
                int ge = bbase + 2 * pidx;
                pb[it] = (ge + 1 < W1_TOT) ? __ldg((const float2*)(W1 + ge))
                                           : make_float2(0.f, 0.f);
            }
        }

        const uint32_t aHiB = (uint32_t)__cvta_generic_to_shared(sAhi[cur]);
        const uint32_t aLoB = (uint32_t)__cvta_generic_to_shared(sAlo[cur]);
        const uint32_t bHiB = (uint32_t)__cvta_generic_to_shared(sBhi[cur]);
        const uint32_t bLoB = (uint32_t)__cvta_generic_to_shared(sBlo[cur]);
        #pragma unroll
        for (int ks = 0; ks < 2; ks++) {
            const uint32_t kbA = (uint32_t)(ks * 16 * 2);
            const uint32_t kbB = (uint32_t)(ks * 16 * NHID * 2);
            uint32_t ahi[2][4], alo[2][4], bh[10], bl[10];
            ldsm4 (ahi[0], aHiB + aOff[0] + kbA);
            ldsm4 (ahi[1], aHiB + aOff[1] + kbA);
            ldsm4 (alo[0], aLoB + aOff[0] + kbA);
            ldsm4 (alo[1], aLoB + aOff[1] + kbA);
            ldsm4t(bh + 0, bHiB + bOff4[0] + kbB);
            ldsm4t(bh + 4, bHiB + bOff4[1] + kbB);
            ldsm2t(bh + 8, bHiB + bOff2 + kbB);
            ldsm4t(bl + 0, bLoB + bOff4[0] + kbB);
            ldsm4t(bl + 4, bLoB + bOff4[1] + kbB);
            ldsm2t(bl + 8, bLoB + bOff2 + kbB);
            #pragma unroll
            for (int mi = 0; mi < 2; mi++)
                #pragma unroll
                for (int ni = 0; ni < 5; ni++) {
                    mma_bf16(acc[mi][ni], ahi[mi], bh + ni * 2);
                    mma_bf16(acc[mi][ni], ahi[mi], bl + ni * 2);
                    mma_bf16(acc[mi][ni], alo[mi], bh + ni * 2);
                }
        }

        if (more) {
            const int nxt = cur ^ 1;
            #pragma unroll
            for (int it = 0; it < 32; it++) {
                int r = wid + it * 4;
                uint16_t hi, lo;
                split_bf16(pa[it], hi, lo);
                sAhi[nxt][r * ASTRIDE + lane] = hi;
                sAlo[nxt][r * ASTRIDE + lane] = lo;
            }
            #pragma unroll
            for (int it = 0; it < 5; it++) {
                int pidx = tid + it * 128;
                uint16_t h0, l0, h1, l1;
                split_bf16(pb[it].x, h0, l0);
                split_bf16(pb[it].y, h1, l1);
                ((uint32_t*)sBhi[nxt])[pidx] = (uint32_t)h0 | ((uint32_t)h1 << 16);
                ((uint32_t*)sBlo[nxt])[pidx] = (uint32_t)l0 | ((uint32_t)l1 << 16);
            }
        }
        __syncthreads();
    }

    const int cbase = (lane & 3) * 2;
    #pragma unroll
    for (int mi = 0; mi < 2; mi++) {
        const int rbase = row0 + wid * 32 + mi * 16 + (lane >> 2);
        #pragma unroll
        for (int ni = 0; ni < 5; ni++) {
            int col = ni * 8 + cbase;
            if (rbase < N_NODES) {
                float2 v = make_float2(acc[mi][ni][0], acc[mi][ni][1]);
                *(float2*)(g_sup1 + (size_t)rbase * NHID + col) = v;
            }
            if (rbase + 8 < N_NODES) {
                float2 v = make_float2(acc[mi][ni][2], acc[mi][ni][3]);
                *(float2*)(g_sup1 + (size_t)(rbase + 8) * NHID + col) = v;
            }
        }
    }
}

// ------- agg1 + bias/relu/dropout + GEMM2 fused (warp per node, batch 8) ------
__global__ void __launch_bounds__(256) agg1_gemm2_kernel(
    const float* __restrict__ b1, const float* __restrict__ mask,
    const float* __restrict__ W2)
{
    __shared__ float w2s[NHID * NCLASS];   // 280, row-major [k][c]
    for (int i = threadIdx.x; i < NHID * NCLASS; i += 256) w2s[i] = W2[i];
    __syncthreads();

    int n = (blockIdx.x * blockDim.x + threadIdx.x) >> 5;
    int lane = threadIdx.x & 31;
    if (n >= N_NODES) return;
    int beg = g_rowptr[n], end = g_rowptr[n + 1];

    float acc0 = 0.0f, acc1 = 0.0f;
    #pragma unroll 1
    for (int e0 = beg; e0 < end; e0 += 8) {
        int2 ed[8];
        #pragma unroll
        for (int j = 0; j < 8; j++) {
            int idx = e0 + j;
            ed[j] = (idx < end) ? __ldg(&g_csr_edge[idx]) : make_int2(0, 0);
        }
        #pragma unroll
        for (int j = 0; j < 8; j++) {
            float w = __int_as_float(ed[j].y);
            const float* row = g_sup1 + (size_t)ed[j].x * NHID;
            acc0 = fmaf(w, __ldg(row + lane), acc0);
            if (lane < 8) acc1 = fmaf(w, __ldg(row + 32 + lane), acc1);
        }
    }
    float h0, h1v = 0.0f;
    {
        float v = fmaxf(acc0 + __ldg(b1 + lane), 0.0f);
        float m = __ldg(mask + (size_t)n * NHID + lane);
        h0 = (m > 0.5f) ? v * 2.0f : 0.0f;
    }
    if (lane < 8) {
        int cidx = 32 + lane;
        float v = fmaxf(acc1 + __ldg(b1 + cidx), 0.0f);
        float m = __ldg(mask + (size_t)n * NHID + cidx);
        h1v = (m > 0.5f) ? v * 2.0f : 0.0f;
    }
    #pragma unroll
    for (int c = 0; c < NCLASS; c++) {
        float p = h0 * w2s[lane * NCLASS + c];
        if (lane < 8) p += h1v * w2s[(32 + lane) * NCLASS + c];
        p += __shfl_xor_sync(0xFFFFFFFFu, p, 16);
        p += __shfl_xor_sync(0xFFFFFFFFu, p, 8);
        p += __shfl_xor_sync(0xFFFFFFFFu, p, 4);
        p += __shfl_xor_sync(0xFFFFFFFFu, p, 2);
        p += __shfl_xor_sync(0xFFFFFFFFu, p, 1);
        if (lane == 0) g_sup2[(size_t)n * NC_PAD + c] = p;
    }
    if (lane == 0) g_sup2[(size_t)n * NC_PAD + NCLASS] = 0.0f;  // pad
}

// ------- agg2 (warp/node, 4 edges x 8 feats) fused with bias + log_softmax ----
__global__ void __launch_bounds__(256) agg2_lsm_kernel(
    const float* __restrict__ b2, float* __restrict__ out)
{
    int n = (blockIdx.x * blockDim.x + threadIdx.x) >> 5;
    int lane = threadIdx.x & 31;
    if (n >= N_NODES) return;
    int beg = g_rowptr[n], end = g_rowptr[n + 1];
    int j = lane >> 3;      // edge sub-slot 0..3
    int f = lane & 7;       // feature 0..7 (7 = pad)

    float acc = 0.0f;
    #pragma unroll 1
    for (int e0 = beg; e0 < end; e0 += 4) {
        int idx = e0 + j;
        int2 ed = (idx < end) ? __ldg(&g_csr_edge[idx]) : make_int2(0, 0);
        float w = __int_as_float(ed.y);
        acc = fmaf(w, __ldg(g_sup2 + (size_t)ed.x * NC_PAD + f), acc);
    }
    acc += __shfl_xor_sync(0xFFFFFFFFu, acc, 8);
    acc += __shfl_xor_sync(0xFFFFFFFFu, acc, 16);

    float z = acc + __ldg(b2 + ((f < NCLASS) ? f : 0));
    float m = (f < NCLASS) ? z : -1e30f;
    m = fmaxf(m, __shfl_xor_sync(0xFFFFFFFFu, m, 1));
    m = fmaxf(m, __shfl_xor_sync(0xFFFFFFFFu, m, 2));
    m = fmaxf(m, __shfl_xor_sync(0xFFFFFFFFu, m, 4));
    float ex = (f < NCLASS) ? __expf(z - m) : 0.0f;
    float s = ex;
    s += __shfl_xor_sync(0xFFFFFFFFu, s, 1);
    s += __shfl_xor_sync(0xFFFFFFFFu, s, 2);
    s += __shfl_xor_sync(0xFFFFFFFFu, s, 4);
    float lse = m + __logf(s);
    if (f < NCLASS && j == 0)
        out[(size_t)n * NCLASS + f] = z - lse;
}

// ---------------- launch -----------------------------------------------------
extern "C" void kernel_launch(void* const* d_in, const int* in_sizes, int n_in,
                              void* d_out, int out_size)
{
    const float* x    = (const float*)d_in[0];
    const int*   src  = (const int*)  d_in[1];
    const int*   dst  = (const int*)  d_in[2];
    const float* ew   = (const float*)d_in[3];
    const float* W1   = (const float*)d_in[4];
    const float* b1   = (const float*)d_in[5];
    const float* W2   = (const float*)d_in[6];
    const float* b2   = (const float*)d_in[7];
    const float* mask = (const float*)d_in[8];
    float* out = (float*)d_out;

    const int E = in_sizes[1];
    const int NBLK_M = (N_NODES + M_TILE - 1) / M_TILE;   // 782

    // One-time side stream + capture-safe events (timing disabled).
    // Host-side handles only; no device memory involved.
    static cudaStream_t s1 = nullptr;
    static cudaEvent_t  evS = nullptr, evF = nullptr;
    if (s1 == nullptr) {
        cudaStreamCreateWithFlags(&s1, cudaStreamNonBlocking);
        cudaEventCreateWithFlags(&evS, cudaEventDisableTiming);
        cudaEventCreateWithFlags(&evF, cudaEventDisableTiming);
    }

    // Fork: CSR build on s1, gemm1 concurrently on the capture (legacy) stream.
    cudaEventRecord(evS, 0);
    cudaStreamWaitEvent(s1, evS, 0);

    // submission idx (kernel launches only):                              idx
    clear_counts_kernel<<<(N_NODES + 255) / 256, 256, 0, s1>>>();       //  0
    hist_kernel<<<(E + 255) / 256, 256, 0, s1>>>(dst, E);               //  1
    scan_part_kernel<<<SCAN_NBLK, SCAN_B, 0, s1>>>();                   //  2
    gemm1_mma_kernel<<<NBLK_M, 128>>>(x, W1);                           //  3  <- profiled (legacy stream)
    scan_top_kernel<<<1, 128, 0, s1>>>();                               //  4
    scan_add_kernel<<<(N_NODES + 255) / 256, 256, 0, s1>>>(E);          //  5
    fill_kernel<<<(E + 255) / 256, 256, 0, s1>>>(src, dst, ew, E);      //  6
    cudaEventRecord(evF, s1);

    // Join: aggregation needs both gemm1 (legacy) and CSR (s1).
    cudaStreamWaitEvent(0, evF, 0);
    agg1_gemm2_kernel<<<(N_NODES * 32 + 255) / 256, 256>>>(b1, mask, W2); // 7
    agg2_lsm_kernel<<<(N_NODES * 32 + 255) / 256, 256>>>(b2, out);      //  8
}